// round 6
// baseline (speedup 1.0000x reference)
#include <cuda_runtime.h>
#include <cuda_fp16.h>
#include <cstdint>

#define B_  64
#define N_  2048
#define I_  16
#define JK_ 1024

typedef unsigned long long ull;

// Scratch: u_hat fp16 [b][n][jk] (256 MB); three s buffers (iter 0,1,2)
__device__ __half g_uhat[(size_t)B_ * N_ * JK_];
__device__ float  g_sb[3][B_ * JK_];

// ---------------- packed fp32x2 helpers (sm_100+) ----------------
static __device__ __forceinline__ ull fma2(ull a, ull b, ull c) {
    ull d;
    asm("fma.rn.f32x2 %0, %1, %2, %3;" : "=l"(d) : "l"(a), "l"(b), "l"(c));
    return d;
}
static __device__ __forceinline__ ull add2(ull a, ull b) {
    ull d;
    asm("add.rn.f32x2 %0, %1, %2;" : "=l"(d) : "l"(a), "l"(b));
    return d;
}
static __device__ __forceinline__ float2 ull2f2(ull v) {
    float2 f;
    asm("mov.b64 {%0, %1}, %2;" : "=f"(f.x), "=f"(f.y) : "l"(v));
    return f;
}
static __device__ __forceinline__ ull packf2(float x, float y) {
    ull r;
    asm("mov.b64 %0, {%1, %2};" : "=l"(r) : "f"(x), "f"(y));
    return r;
}
static __device__ __forceinline__ ull dupf(float x) {
    ull r;
    asm("mov.b64 %0, {%1, %1};" : "=l"(r) : "f"(x));
    return r;
}
static __device__ __forceinline__ ull h2f2(unsigned int h) {
    __half2 hh = *reinterpret_cast<__half2*>(&h);
    float2 f = __half22float2(hh);
    return packf2(f.x, f.y);
}
static __device__ __forceinline__ void red4(float* p, float4 v) {
    asm volatile("red.global.add.v4.f32 [%0], {%1,%2,%3,%4};"
                 :: "l"(p), "f"(v.x), "f"(v.y), "f"(v.z), "f"(v.w) : "memory");
}

__global__ void k_pad() {}

__global__ void __launch_bounds__(1024) k_init() {
    int idx = blockIdx.x * 1024 + threadIdx.x;   // grid 192 -> 196608
    (&g_sb[0][0])[idx] = 0.0f;
}

// ---------------- fused u_hat generation + iteration-0 s ----------------
// Persistent: grid 296 = 148 n-strips x 2 jk-halves, double-buffered staging.
// Writes u_hat fp16; accumulates s0 = (1/32) sum_n u_hat in REGISTERS
// (thread's jk/b tile is t-invariant) — no smem S0, no epilogue LDS/STS.
__global__ void __launch_bounds__(512, 1) k_uhat(const float* __restrict__ inp,
                                                 const float* __restrict__ W) {
    extern __shared__ float sm[];
    float* Wb0 = sm;                 // 16i x 512jk
    float* Wb1 = sm + 8192;
    float* Xs0 = sm + 16384;         // 16i x 64b
    float* Xs1 = sm + 17408;         // total 18432 floats = 72 KB

    const int tid = threadIdx.x;
    const int jkh = blockIdx.x & 1;
    const int idx = blockIdx.x >> 1;   // 0..147

    const int jkg = jkh * 512 + tid;
    const int wj = jkg >> 5, wk = jkg & 31;
    const float* wbase = W + (size_t)wj * N_ * 512 + wk * 16;
    const int xb = tid >> 3, xi = (tid & 7) * 2;
    const float* xbase = inp + (size_t)xb * N_ * 16 + xi;

    const int jkq = tid & 63;      // jk = jkq*4 (+0..3) and 256+jkq*4
    const int bq  = tid >> 6;      // 8-b group

    const int total = (N_ - idx + 147) / 148;

    float4 wr0, wr1, wr2, wr3; float2 xr;
    {
        const float4* ws = reinterpret_cast<const float4*>(wbase + (size_t)idx * 512);
        wr0 = ws[0]; wr1 = ws[1]; wr2 = ws[2]; wr3 = ws[3];
        xr = *reinterpret_cast<const float2*>(xbase + (size_t)idx * 16);
        Wb0[0*512+tid]=wr0.x;  Wb0[1*512+tid]=wr0.y;  Wb0[2*512+tid]=wr0.z;  Wb0[3*512+tid]=wr0.w;
        Wb0[4*512+tid]=wr1.x;  Wb0[5*512+tid]=wr1.y;  Wb0[6*512+tid]=wr1.z;  Wb0[7*512+tid]=wr1.w;
        Wb0[8*512+tid]=wr2.x;  Wb0[9*512+tid]=wr2.y;  Wb0[10*512+tid]=wr2.z; Wb0[11*512+tid]=wr2.w;
        Wb0[12*512+tid]=wr3.x; Wb0[13*512+tid]=wr3.y; Wb0[14*512+tid]=wr3.z; Wb0[15*512+tid]=wr3.w;
        Xs0[xi * 64 + xb] = xr.x;
        Xs0[(xi + 1) * 64 + xb] = xr.y;
    }

    // register s0 accumulator (same layout as acc)
    ull s0a[8][4];
    #pragma unroll
    for (int m = 0; m < 8; m++)
        #pragma unroll
        for (int p = 0; p < 4; p++) s0a[m][p] = 0ull;

    for (int t = 0; t < total; t++) {
        __syncthreads();
        const int ncur = idx + t * 148;
        const bool more = (t + 1 < total);
        if (more) {
            const int nn = ncur + 148;
            const float4* ws = reinterpret_cast<const float4*>(wbase + (size_t)nn * 512);
            wr0 = ws[0]; wr1 = ws[1]; wr2 = ws[2]; wr3 = ws[3];
            xr = *reinterpret_cast<const float2*>(xbase + (size_t)nn * 16);
        }
        const float* Wc = (t & 1) ? Wb1 : Wb0;
        const float* Xc = (t & 1) ? Xs1 : Xs0;

        ull acc[8][4];
        #pragma unroll
        for (int m = 0; m < 8; m++)
            #pragma unroll
            for (int p = 0; p < 4; p++) acc[m][p] = 0ull;

        #pragma unroll
        for (int i = 0; i < 16; i++) {
            float4 wa = *reinterpret_cast<const float4*>(Wc + i * 512 + jkq * 4);
            float4 wb = *reinterpret_cast<const float4*>(Wc + i * 512 + 256 + jkq * 4);
            ull wd0 = dupf(wa.x), wd1 = dupf(wa.y), wd2 = dupf(wa.z), wd3 = dupf(wa.w);
            ull wd4 = dupf(wb.x), wd5 = dupf(wb.y), wd6 = dupf(wb.z), wd7 = dupf(wb.w);
            ulonglong2 xu0 = *reinterpret_cast<const ulonglong2*>(Xc + i * 64 + bq * 8);
            ulonglong2 xu1 = *reinterpret_cast<const ulonglong2*>(Xc + i * 64 + bq * 8 + 4);
            ull xp0 = xu0.x, xp1 = xu0.y, xp2 = xu1.x, xp3 = xu1.y;
            acc[0][0]=fma2(wd0,xp0,acc[0][0]); acc[0][1]=fma2(wd0,xp1,acc[0][1]);
            acc[0][2]=fma2(wd0,xp2,acc[0][2]); acc[0][3]=fma2(wd0,xp3,acc[0][3]);
            acc[1][0]=fma2(wd1,xp0,acc[1][0]); acc[1][1]=fma2(wd1,xp1,acc[1][1]);
            acc[1][2]=fma2(wd1,xp2,acc[1][2]); acc[1][3]=fma2(wd1,xp3,acc[1][3]);
            acc[2][0]=fma2(wd2,xp0,acc[2][0]); acc[2][1]=fma2(wd2,xp1,acc[2][1]);
            acc[2][2]=fma2(wd2,xp2,acc[2][2]); acc[2][3]=fma2(wd2,xp3,acc[2][3]);
            acc[3][0]=fma2(wd3,xp0,acc[3][0]); acc[3][1]=fma2(wd3,xp1,acc[3][1]);
            acc[3][2]=fma2(wd3,xp2,acc[3][2]); acc[3][3]=fma2(wd3,xp3,acc[3][3]);
            acc[4][0]=fma2(wd4,xp0,acc[4][0]); acc[4][1]=fma2(wd4,xp1,acc[4][1]);
            acc[4][2]=fma2(wd4,xp2,acc[4][2]); acc[4][3]=fma2(wd4,xp3,acc[4][3]);
            acc[5][0]=fma2(wd5,xp0,acc[5][0]); acc[5][1]=fma2(wd5,xp1,acc[5][1]);
            acc[5][2]=fma2(wd5,xp2,acc[5][2]); acc[5][3]=fma2(wd5,xp3,acc[5][3]);
            acc[6][0]=fma2(wd6,xp0,acc[6][0]); acc[6][1]=fma2(wd6,xp1,acc[6][1]);
            acc[6][2]=fma2(wd6,xp2,acc[6][2]); acc[6][3]=fma2(wd6,xp3,acc[6][3]);
            acc[7][0]=fma2(wd7,xp0,acc[7][0]); acc[7][1]=fma2(wd7,xp1,acc[7][1]);
            acc[7][2]=fma2(wd7,xp2,acc[7][2]); acc[7][3]=fma2(wd7,xp3,acc[7][3]);
        }

        if (more) {
            float* Wn = (t & 1) ? Wb0 : Wb1;
            float* Xn = (t & 1) ? Xs0 : Xs1;
            Wn[0*512+tid]=wr0.x;  Wn[1*512+tid]=wr0.y;  Wn[2*512+tid]=wr0.z;  Wn[3*512+tid]=wr0.w;
            Wn[4*512+tid]=wr1.x;  Wn[5*512+tid]=wr1.y;  Wn[6*512+tid]=wr1.z;  Wn[7*512+tid]=wr1.w;
            Wn[8*512+tid]=wr2.x;  Wn[9*512+tid]=wr2.y;  Wn[10*512+tid]=wr2.z; Wn[11*512+tid]=wr2.w;
            Wn[12*512+tid]=wr3.x; Wn[13*512+tid]=wr3.y; Wn[14*512+tid]=wr3.z; Wn[15*512+tid]=wr3.w;
            Xn[xi * 64 + xb] = xr.x;
            Xn[(xi + 1) * 64 + xb] = xr.y;
        }

        // epilogue: s0 regs += acc; u_hat fp16 store
        #pragma unroll
        for (int m = 0; m < 8; m++)
            #pragma unroll
            for (int p = 0; p < 4; p++) s0a[m][p] = add2(s0a[m][p], acc[m][p]);

        #pragma unroll
        for (int p = 0; p < 4; p++) {
            float2 a0 = ull2f2(acc[0][p]), a1 = ull2f2(acc[1][p]);
            float2 a2 = ull2f2(acc[2][p]), a3 = ull2f2(acc[3][p]);
            float2 a4 = ull2f2(acc[4][p]), a5 = ull2f2(acc[5][p]);
            float2 a6 = ull2f2(acc[6][p]), a7 = ull2f2(acc[7][p]);
            #pragma unroll
            for (int e = 0; e < 2; e++) {
                const int bg = bq * 8 + 2 * p + e;
                float f0 = e ? a0.y : a0.x, f1 = e ? a1.y : a1.x;
                float f2 = e ? a2.y : a2.x, f3 = e ? a3.y : a3.x;
                float f4 = e ? a4.y : a4.x, f5 = e ? a5.y : a5.x;
                float f6 = e ? a6.y : a6.x, f7 = e ? a7.y : a7.x;

                __half2 hA0 = __floats2half2_rn(f0, f1), hA1 = __floats2half2_rn(f2, f3);
                __half2 hB0 = __floats2half2_rn(f4, f5), hB1 = __floats2half2_rn(f6, f7);
                __half* up = g_uhat + ((size_t)bg * N_ + ncur) * JK_ + jkh * 512;
                uint2 vA, vB;
                vA.x = *reinterpret_cast<unsigned int*>(&hA0);
                vA.y = *reinterpret_cast<unsigned int*>(&hA1);
                vB.x = *reinterpret_cast<unsigned int*>(&hB0);
                vB.y = *reinterpret_cast<unsigned int*>(&hB1);
                *reinterpret_cast<uint2*>(up + jkq * 4) = vA;
                *reinterpret_cast<uint2*>(up + 256 + jkq * 4) = vB;
            }
        }
    }

    // flush register s0 (scaled by 1/32) via global reductions
    #pragma unroll
    for (int p = 0; p < 4; p++) {
        float2 a0 = ull2f2(s0a[0][p]), a1 = ull2f2(s0a[1][p]);
        float2 a2 = ull2f2(s0a[2][p]), a3 = ull2f2(s0a[3][p]);
        float2 a4 = ull2f2(s0a[4][p]), a5 = ull2f2(s0a[5][p]);
        float2 a6 = ull2f2(s0a[6][p]), a7 = ull2f2(s0a[7][p]);
        #pragma unroll
        for (int e = 0; e < 2; e++) {
            const int bg = bq * 8 + 2 * p + e;
            float f0 = (e ? a0.y : a0.x) * 0.03125f, f1 = (e ? a1.y : a1.x) * 0.03125f;
            float f2 = (e ? a2.y : a2.x) * 0.03125f, f3 = (e ? a3.y : a3.x) * 0.03125f;
            float f4 = (e ? a4.y : a4.x) * 0.03125f, f5 = (e ? a5.y : a5.x) * 0.03125f;
            float f6 = (e ? a6.y : a6.x) * 0.03125f, f7 = (e ? a7.y : a7.x) * 0.03125f;
            float* dst = &g_sb[0][bg * JK_ + jkh * 512];
            red4(dst + jkq * 4,       make_float4(f0, f1, f2, f3));
            red4(dst + 256 + jkq * 4, make_float4(f4, f5, f6, f7));
        }
    }
}

// ---------------- fused squash + routing pass ----------------
// occ forced to 3 CTAs/SM (regs <= ~85) for latency hiding.
__global__ void __launch_bounds__(256, 3)
k_route(int ia, int ib, int io, int two) {
    __shared__ float V_sm[1024];
    __shared__ float ws[8 * 1024];     // per-warp s partials

    const float* sa = g_sb[ia];
    const float* sb = g_sb[ib];
    float* sout = g_sb[io];

    const int chunk = blockIdx.x;      // 0..31
    const int b     = blockIdx.y;      // 0..63
    const int tid   = threadIdx.x;     // 256
    const int warp  = tid >> 5;
    const int lane  = tid & 31;

    // --- build V[j][k] = squash(sa) [+ squash(sb)] ---
    #pragma unroll
    for (int r = 0; r < 4; r++) {
        int j = warp * 4 + r;
        float va = sa[b * JK_ + j * 32 + lane];
        float sq = va * va;
        #pragma unroll
        for (int o = 16; o; o >>= 1) sq += __shfl_xor_sync(0xffffffffu, sq, o);
        float val = (sq / ((1.0f + sq) * sqrtf(sq + 1e-7f))) * va;
        if (two) {
            float vb = sb[b * JK_ + j * 32 + lane];
            float sqb = vb * vb;
            #pragma unroll
            for (int o = 16; o; o >>= 1) sqb += __shfl_xor_sync(0xffffffffu, sqb, o);
            val += (sqb / ((1.0f + sqb) * sqrtf(sqb + 1e-7f))) * vb;
        }
        V_sm[j * 32 + lane] = val;
    }
    __syncthreads();

    // lane's V slice: for q, jk = q*256 + lane*8 .. +7
    ull vq[4][4];
    #pragma unroll
    for (int q = 0; q < 4; q++) {
        float4 a = *reinterpret_cast<const float4*>(V_sm + q * 256 + lane * 8);
        float4 c = *reinterpret_cast<const float4*>(V_sm + q * 256 + lane * 8 + 4);
        vq[q][0] = packf2(a.x, a.y); vq[q][1] = packf2(a.z, a.w);
        vq[q][2] = packf2(c.x, c.y); vq[q][3] = packf2(c.z, c.w);
    }

    ull sacc[4][4];
    #pragma unroll
    for (int q = 0; q < 4; q++)
        #pragma unroll
        for (int m = 0; m < 4; m++) sacc[q][m] = 0ull;

    const char* row0 = reinterpret_cast<const char*>(
        g_uhat + ((size_t)b * N_ + (size_t)(chunk * 64 + warp * 8)) * JK_) + lane * 16;

    #pragma unroll 2
    for (int t = 0; t < 8; t++) {
        const char* rc = row0 + (size_t)t * 2048;
        uint4 cur0 = *reinterpret_cast<const uint4*>(rc);
        uint4 cur1 = *reinterpret_cast<const uint4*>(rc + 512);
        uint4 cur2 = *reinterpret_cast<const uint4*>(rc + 1024);
        uint4 cur3 = *reinterpret_cast<const uint4*>(rc + 1536);
        uint4 c4[4] = {cur0, cur1, cur2, cur3};
        float e[4];
        #pragma unroll
        for (int q = 0; q < 4; q++) {
            ull u0 = h2f2(c4[q].x), u1 = h2f2(c4[q].y);
            ull u2 = h2f2(c4[q].z), u3 = h2f2(c4[q].w);
            ull d = fma2(u0, vq[q][0], fma2(u1, vq[q][1],
                    fma2(u2, vq[q][2], fma2(u3, vq[q][3], 0ull))));
            float2 df = ull2f2(d);
            float bp = df.x + df.y;
            bp += __shfl_xor_sync(0xffffffffu, bp, 1);
            bp += __shfl_xor_sync(0xffffffffu, bp, 2);
            e[q] = __expf(bp);          // logits bounded; no max needed
        }
        float tot = e[0] + e[1] + e[2] + e[3];
        tot += __shfl_xor_sync(0xffffffffu, tot, 4);
        tot += __shfl_xor_sync(0xffffffffu, tot, 8);
        tot += __shfl_xor_sync(0xffffffffu, tot, 16);
        float inv = __fdividef(1.0f, tot);
        #pragma unroll
        for (int q = 0; q < 4; q++) {
            ull cq2 = dupf(e[q] * inv);
            ull u0 = h2f2(c4[q].x), u1 = h2f2(c4[q].y);
            ull u2 = h2f2(c4[q].z), u3 = h2f2(c4[q].w);
            sacc[q][0] = fma2(cq2, u0, sacc[q][0]);
            sacc[q][1] = fma2(cq2, u1, sacc[q][1]);
            sacc[q][2] = fma2(cq2, u2, sacc[q][2]);
            sacc[q][3] = fma2(cq2, u3, sacc[q][3]);
        }
    }

    // per-warp private store (no atomics)
    #pragma unroll
    for (int q = 0; q < 4; q++) {
        float2 f0 = ull2f2(sacc[q][0]), f1 = ull2f2(sacc[q][1]);
        float2 f2 = ull2f2(sacc[q][2]), f3 = ull2f2(sacc[q][3]);
        float* wp = ws + warp * 1024 + q * 256 + lane * 8;
        *reinterpret_cast<float4*>(wp)     = make_float4(f0.x, f0.y, f1.x, f1.y);
        *reinterpret_cast<float4*>(wp + 4) = make_float4(f2.x, f2.y, f3.x, f3.y);
    }
    __syncthreads();

    // cross-warp tree reduce + global flush
    float4 a = *reinterpret_cast<const float4*>(ws + tid * 4);
    #pragma unroll
    for (int w = 1; w < 8; w++) {
        float4 x = *reinterpret_cast<const float4*>(ws + w * 1024 + tid * 4);
        a.x += x.x; a.y += x.y; a.z += x.z; a.w += x.w;
    }
    red4(sout + b * JK_ + tid * 4, a);
}

// ---------------- final squash ----------------
__global__ void __launch_bounds__(1024) k_squash_final(float* __restrict__ out) {
    const int b   = blockIdx.x;
    const int tid = threadIdx.x;      // warp = j, lane = k
    float sv = g_sb[2][b * JK_ + tid];
    float sq = sv * sv;
    #pragma unroll
    for (int o = 16; o; o >>= 1) sq += __shfl_xor_sync(0xffffffffu, sq, o);
    out[b * JK_ + tid] = (sq / ((1.0f + sq) * sqrtf(sq + 1e-7f))) * sv;
}

extern "C" void kernel_launch(void* const* d_in, const int* in_sizes, int n_in,
                              void* d_out, int out_size) {
    const float* inp = (const float*)d_in[0];   // [64, 2048, 16]
    const float* W   = (const float*)d_in[1];   // [32, 2048, 32, 16]
    float* out = (float*)d_out;                 // [64, 32, 32]

    cudaFuncSetAttribute(k_uhat, cudaFuncAttributeMaxDynamicSharedMemorySize, 73728);

    k_init<<<192, 1024>>>();                    // zero s0,s1,s2
    k_pad<<<1, 32>>>();                         // align ncu capture (#4) ...
    k_pad<<<1, 32>>>();                         // ... on k_uhat this round
    k_uhat<<<296, 512, 73728>>>(inp, W);        // u_hat + s0 (register accum)
    k_route<<<dim3(32, 64), 256>>>(0, 0, 1, 0); // V0 -> s1
    k_route<<<dim3(32, 64), 256>>>(0, 1, 2, 1); // V0+V1 -> s2
    k_squash_final<<<64, 1024>>>(out);
}

// round 7
// speedup vs baseline: 1.1967x; 1.1967x over previous
#include <cuda_runtime.h>
#include <cuda_fp16.h>
#include <cstdint>

#define B_  64
#define N_  2048
#define I_  16
#define JK_ 1024

typedef unsigned long long ull;

// Scratch: u_hat fp16 [b][n][jk] (256 MB); three s buffers (iter 0,1,2)
__device__ __half g_uhat[(size_t)B_ * N_ * JK_];
__device__ float  g_sb[3][B_ * JK_];

// ---------------- packed fp32x2 helpers (sm_100+) ----------------
static __device__ __forceinline__ ull fma2(ull a, ull b, ull c) {
    ull d;
    asm("fma.rn.f32x2 %0, %1, %2, %3;" : "=l"(d) : "l"(a), "l"(b), "l"(c));
    return d;
}
static __device__ __forceinline__ ull add2(ull a, ull b) {
    ull d;
    asm("add.rn.f32x2 %0, %1, %2;" : "=l"(d) : "l"(a), "l"(b));
    return d;
}
static __device__ __forceinline__ float2 ull2f2(ull v) {
    float2 f;
    asm("mov.b64 {%0, %1}, %2;" : "=f"(f.x), "=f"(f.y) : "l"(v));
    return f;
}
static __device__ __forceinline__ ull packf2(float x, float y) {
    ull r;
    asm("mov.b64 %0, {%1, %2};" : "=l"(r) : "f"(x), "f"(y));
    return r;
}
static __device__ __forceinline__ ull dupf(float x) {
    ull r;
    asm("mov.b64 %0, {%1, %1};" : "=l"(r) : "f"(x));
    return r;
}
static __device__ __forceinline__ ull h2f2(unsigned int h) {
    __half2 hh = *reinterpret_cast<__half2*>(&h);
    float2 f = __half22float2(hh);
    return packf2(f.x, f.y);
}
static __device__ __forceinline__ void red4(float* p, float4 v) {
    asm volatile("red.global.add.v4.f32 [%0], {%1,%2,%3,%4};"
                 :: "l"(p), "f"(v.x), "f"(v.y), "f"(v.z), "f"(v.w) : "memory");
}

__global__ void k_pad() {}

__global__ void __launch_bounds__(1024) k_init() {
    int idx = blockIdx.x * 1024 + threadIdx.x;   // grid 192 -> 196608
    (&g_sb[0][0])[idx] = 0.0f;
}

// ---------------- fused u_hat generation + iteration-0 s ----------------
// Grid 1184 = 148 n-strips x 8 jk-eighths, 256 threads, 3 CTAs/SM (24 warps).
// Warp w -> b in [8w,8w+8); lane l -> jk_local in [4l,4l+4).
// W staged transposed [i][jk]; X staged DUPLICATED [i][(b,b)] so the inner
// loop is pure LDS.128 + fma2 (no MOV dups). s0 accumulated in registers.
__global__ void __launch_bounds__(256, 3) k_uhat(const float* __restrict__ inp,
                                                 const float* __restrict__ W) {
    __shared__ float Ws[2][16 * 128];   // [buf][i][jk_local]  2x8KB
    __shared__ float Xd[2][16 * 128];   // [buf][i][2b dup]    2x8KB

    const int tid = threadIdx.x;
    const int jke = blockIdx.x & 7;     // jk-eighth
    const int idx = blockIdx.x >> 3;    // n-strip 0..147

    const int w = tid >> 5;             // warp = b-group
    const int l = tid & 31;             // lane = jk-quad

    // staging assignments
    const int sjk   = tid >> 1;             // 0..127 (jk row to stage)
    const int shalf = (tid & 1) * 8;        // i half 0 or 8
    const int jkg   = jke * 128 + sjk;
    const float* wsrc = W + ((size_t)(jkg >> 5) * N_) * 512 + (size_t)(jkg & 31) * 16 + shalf;
    const int xb = tid & 63;
    const int xi = (tid >> 6) * 4;           // 0,4,8,12
    const float* xsrc = inp + (size_t)xb * N_ * 16 + xi;

    const int total = (N_ - idx + 147) / 148;

    float4 wr0, wr1, xr;
    {   // prologue: tile 0 into buffer 0
        const float* ws = wsrc + (size_t)idx * 512;
        wr0 = *reinterpret_cast<const float4*>(ws);
        wr1 = *reinterpret_cast<const float4*>(ws + 4);
        xr  = *reinterpret_cast<const float4*>(xsrc + (size_t)idx * 16);
        Ws[0][(shalf + 0) * 128 + sjk] = wr0.x;
        Ws[0][(shalf + 1) * 128 + sjk] = wr0.y;
        Ws[0][(shalf + 2) * 128 + sjk] = wr0.z;
        Ws[0][(shalf + 3) * 128 + sjk] = wr0.w;
        Ws[0][(shalf + 4) * 128 + sjk] = wr1.x;
        Ws[0][(shalf + 5) * 128 + sjk] = wr1.y;
        Ws[0][(shalf + 6) * 128 + sjk] = wr1.z;
        Ws[0][(shalf + 7) * 128 + sjk] = wr1.w;
        *reinterpret_cast<float2*>(&Xd[0][(xi + 0) * 128 + 2 * xb]) = make_float2(xr.x, xr.x);
        *reinterpret_cast<float2*>(&Xd[0][(xi + 1) * 128 + 2 * xb]) = make_float2(xr.y, xr.y);
        *reinterpret_cast<float2*>(&Xd[0][(xi + 2) * 128 + 2 * xb]) = make_float2(xr.z, xr.z);
        *reinterpret_cast<float2*>(&Xd[0][(xi + 3) * 128 + 2 * xb]) = make_float2(xr.w, xr.w);
    }

    ull s0a[2][8];
    #pragma unroll
    for (int pr = 0; pr < 2; pr++)
        #pragma unroll
        for (int b = 0; b < 8; b++) s0a[pr][b] = 0ull;

    // per-thread output base: b = 8w, jk = jke*128 + 4l
    __half* ubase = g_uhat + ((size_t)(8 * w) * N_) * JK_ + jke * 128 + 4 * l;

    for (int t = 0; t < total; t++) {
        __syncthreads();
        const int ncur = idx + t * 148;
        const bool more = (t + 1 < total);
        if (more) {
            const int nn = ncur + 148;
            const float* ws = wsrc + (size_t)nn * 512;
            wr0 = *reinterpret_cast<const float4*>(ws);
            wr1 = *reinterpret_cast<const float4*>(ws + 4);
            xr  = *reinterpret_cast<const float4*>(xsrc + (size_t)nn * 16);
        }
        const float* Wc = Ws[t & 1];
        const float* Xc = Xd[t & 1];

        ull acc[2][8];
        #pragma unroll
        for (int pr = 0; pr < 2; pr++)
            #pragma unroll
            for (int b = 0; b < 8; b++) acc[pr][b] = 0ull;

        #pragma unroll
        for (int i = 0; i < 16; i++) {
            ulonglong2 wv  = *reinterpret_cast<const ulonglong2*>(Wc + i * 128 + 4 * l);
            ulonglong2 x01 = *reinterpret_cast<const ulonglong2*>(Xc + i * 128 + 16 * w);
            ulonglong2 x23 = *reinterpret_cast<const ulonglong2*>(Xc + i * 128 + 16 * w + 4);
            ulonglong2 x45 = *reinterpret_cast<const ulonglong2*>(Xc + i * 128 + 16 * w + 8);
            ulonglong2 x67 = *reinterpret_cast<const ulonglong2*>(Xc + i * 128 + 16 * w + 12);
            acc[0][0] = fma2(wv.x, x01.x, acc[0][0]); acc[1][0] = fma2(wv.y, x01.x, acc[1][0]);
            acc[0][1] = fma2(wv.x, x01.y, acc[0][1]); acc[1][1] = fma2(wv.y, x01.y, acc[1][1]);
            acc[0][2] = fma2(wv.x, x23.x, acc[0][2]); acc[1][2] = fma2(wv.y, x23.x, acc[1][2]);
            acc[0][3] = fma2(wv.x, x23.y, acc[0][3]); acc[1][3] = fma2(wv.y, x23.y, acc[1][3]);
            acc[0][4] = fma2(wv.x, x45.x, acc[0][4]); acc[1][4] = fma2(wv.y, x45.x, acc[1][4]);
            acc[0][5] = fma2(wv.x, x45.y, acc[0][5]); acc[1][5] = fma2(wv.y, x45.y, acc[1][5]);
            acc[0][6] = fma2(wv.x, x67.x, acc[0][6]); acc[1][6] = fma2(wv.y, x67.x, acc[1][6]);
            acc[0][7] = fma2(wv.x, x67.y, acc[0][7]); acc[1][7] = fma2(wv.y, x67.y, acc[1][7]);
        }

        if (more) {   // stage prefetched tile into the other buffer
            float* Wn = Ws[(t + 1) & 1];
            float* Xn = Xd[(t + 1) & 1];
            Wn[(shalf + 0) * 128 + sjk] = wr0.x;
            Wn[(shalf + 1) * 128 + sjk] = wr0.y;
            Wn[(shalf + 2) * 128 + sjk] = wr0.z;
            Wn[(shalf + 3) * 128 + sjk] = wr0.w;
            Wn[(shalf + 4) * 128 + sjk] = wr1.x;
            Wn[(shalf + 5) * 128 + sjk] = wr1.y;
            Wn[(shalf + 6) * 128 + sjk] = wr1.z;
            Wn[(shalf + 7) * 128 + sjk] = wr1.w;
            *reinterpret_cast<float2*>(&Xn[(xi + 0) * 128 + 2 * xb]) = make_float2(xr.x, xr.x);
            *reinterpret_cast<float2*>(&Xn[(xi + 1) * 128 + 2 * xb]) = make_float2(xr.y, xr.y);
            *reinterpret_cast<float2*>(&Xn[(xi + 2) * 128 + 2 * xb]) = make_float2(xr.z, xr.z);
            *reinterpret_cast<float2*>(&Xn[(xi + 3) * 128 + 2 * xb]) = make_float2(xr.w, xr.w);
        }

        // epilogue: s0 += acc; store u_hat fp16 (coalesced STG.64 per b)
        #pragma unroll
        for (int b = 0; b < 8; b++) {
            s0a[0][b] = add2(s0a[0][b], acc[0][b]);
            s0a[1][b] = add2(s0a[1][b], acc[1][b]);
            float2 fa = ull2f2(acc[0][b]);
            float2 fb = ull2f2(acc[1][b]);
            __half2 h0 = __floats2half2_rn(fa.x, fa.y);
            __half2 h1 = __floats2half2_rn(fb.x, fb.y);
            uint2 v;
            v.x = *reinterpret_cast<unsigned int*>(&h0);
            v.y = *reinterpret_cast<unsigned int*>(&h1);
            *reinterpret_cast<uint2*>(ubase + ((size_t)b * N_ + ncur) * JK_) = v;
        }
    }

    // flush s0 (scaled by 1/32) via vector reductions (coalesced)
    #pragma unroll
    for (int b = 0; b < 8; b++) {
        float2 fa = ull2f2(s0a[0][b]);
        float2 fb = ull2f2(s0a[1][b]);
        red4(&g_sb[0][(8 * w + b) * JK_ + jke * 128 + 4 * l],
             make_float4(fa.x * 0.03125f, fa.y * 0.03125f,
                         fb.x * 0.03125f, fb.y * 0.03125f));
    }
}

// ---------------- fused squash + routing pass (R5 version, measured 67us) ----------------
__global__ void __launch_bounds__(256, 2)
k_route(int ia, int ib, int io, int two) {
    __shared__ float V_sm[1024];
    __shared__ float ws[8 * 1024];     // per-warp s partials

    const float* sa = g_sb[ia];
    const float* sb = g_sb[ib];
    float* sout = g_sb[io];

    const int chunk = blockIdx.x;      // 0..31
    const int b     = blockIdx.y;      // 0..63
    const int tid   = threadIdx.x;     // 256
    const int warp  = tid >> 5;
    const int lane  = tid & 31;

    // --- build V[j][k] = squash(sa) [+ squash(sb)] ---
    #pragma unroll
    for (int r = 0; r < 4; r++) {
        int j = warp * 4 + r;
        float va = sa[b * JK_ + j * 32 + lane];
        float sq = va * va;
        #pragma unroll
        for (int o = 16; o; o >>= 1) sq += __shfl_xor_sync(0xffffffffu, sq, o);
        float val = (sq / ((1.0f + sq) * sqrtf(sq + 1e-7f))) * va;
        if (two) {
            float vb = sb[b * JK_ + j * 32 + lane];
            float sqb = vb * vb;
            #pragma unroll
            for (int o = 16; o; o >>= 1) sqb += __shfl_xor_sync(0xffffffffu, sqb, o);
            val += (sqb / ((1.0f + sqb) * sqrtf(sqb + 1e-7f))) * vb;
        }
        V_sm[j * 32 + lane] = val;
    }
    __syncthreads();

    // lane's V slice: for q, jk = q*256 + lane*8 .. +7
    ull vq[4][4];
    #pragma unroll
    for (int q = 0; q < 4; q++) {
        float4 a = *reinterpret_cast<const float4*>(V_sm + q * 256 + lane * 8);
        float4 c = *reinterpret_cast<const float4*>(V_sm + q * 256 + lane * 8 + 4);
        vq[q][0] = packf2(a.x, a.y); vq[q][1] = packf2(a.z, a.w);
        vq[q][2] = packf2(c.x, c.y); vq[q][3] = packf2(c.z, c.w);
    }

    ull sacc[4][4];
    #pragma unroll
    for (int q = 0; q < 4; q++)
        #pragma unroll
        for (int m = 0; m < 4; m++) sacc[q][m] = 0ull;

    const char* row0 = reinterpret_cast<const char*>(
        g_uhat + ((size_t)b * N_ + (size_t)(chunk * 64 + warp * 8)) * JK_) + lane * 16;

    uint4 cur0, cur1, cur2, cur3, nxt0, nxt1, nxt2, nxt3;
    cur0 = *reinterpret_cast<const uint4*>(row0);
    cur1 = *reinterpret_cast<const uint4*>(row0 + 512);
    cur2 = *reinterpret_cast<const uint4*>(row0 + 1024);
    cur3 = *reinterpret_cast<const uint4*>(row0 + 1536);

    #pragma unroll
    for (int t = 0; t < 8; t++) {
        if (t < 7) {
            const char* rn = row0 + (size_t)(t + 1) * 2048;
            nxt0 = *reinterpret_cast<const uint4*>(rn);
            nxt1 = *reinterpret_cast<const uint4*>(rn + 512);
            nxt2 = *reinterpret_cast<const uint4*>(rn + 1024);
            nxt3 = *reinterpret_cast<const uint4*>(rn + 1536);
        }
        uint4 c4[4] = {cur0, cur1, cur2, cur3};
        float e[4];
        #pragma unroll
        for (int q = 0; q < 4; q++) {
            ull u0 = h2f2(c4[q].x), u1 = h2f2(c4[q].y);
            ull u2 = h2f2(c4[q].z), u3 = h2f2(c4[q].w);
            ull d = fma2(u0, vq[q][0], fma2(u1, vq[q][1],
                    fma2(u2, vq[q][2], fma2(u3, vq[q][3], 0ull))));
            float2 df = ull2f2(d);
            float bp = df.x + df.y;
            bp += __shfl_xor_sync(0xffffffffu, bp, 1);
            bp += __shfl_xor_sync(0xffffffffu, bp, 2);
            e[q] = __expf(bp);          // logits bounded; no max needed
        }
        float tot = e[0] + e[1] + e[2] + e[3];
        tot += __shfl_xor_sync(0xffffffffu, tot, 4);
        tot += __shfl_xor_sync(0xffffffffu, tot, 8);
        tot += __shfl_xor_sync(0xffffffffu, tot, 16);
        float inv = __fdividef(1.0f, tot);
        #pragma unroll
        for (int q = 0; q < 4; q++) {
            ull cq2 = dupf(e[q] * inv);
            ull u0 = h2f2(c4[q].x), u1 = h2f2(c4[q].y);
            ull u2 = h2f2(c4[q].z), u3 = h2f2(c4[q].w);
            sacc[q][0] = fma2(cq2, u0, sacc[q][0]);
            sacc[q][1] = fma2(cq2, u1, sacc[q][1]);
            sacc[q][2] = fma2(cq2, u2, sacc[q][2]);
            sacc[q][3] = fma2(cq2, u3, sacc[q][3]);
        }
        if (t < 7) { cur0 = nxt0; cur1 = nxt1; cur2 = nxt2; cur3 = nxt3; }
    }

    // per-warp private store (no atomics)
    #pragma unroll
    for (int q = 0; q < 4; q++) {
        float2 f0 = ull2f2(sacc[q][0]), f1 = ull2f2(sacc[q][1]);
        float2 f2 = ull2f2(sacc[q][2]), f3 = ull2f2(sacc[q][3]);
        float* wp = ws + warp * 1024 + q * 256 + lane * 8;
        *reinterpret_cast<float4*>(wp)     = make_float4(f0.x, f0.y, f1.x, f1.y);
        *reinterpret_cast<float4*>(wp + 4) = make_float4(f2.x, f2.y, f3.x, f3.y);
    }
    __syncthreads();

    // cross-warp tree reduce + global flush
    float4 a = *reinterpret_cast<const float4*>(ws + tid * 4);
    #pragma unroll
    for (int w = 1; w < 8; w++) {
        float4 x = *reinterpret_cast<const float4*>(ws + w * 1024 + tid * 4);
        a.x += x.x; a.y += x.y; a.z += x.z; a.w += x.w;
    }
    red4(sout + b * JK_ + tid * 4, a);
}

// ---------------- final squash ----------------
__global__ void __launch_bounds__(1024) k_squash_final(float* __restrict__ out) {
    const int b   = blockIdx.x;
    const int tid = threadIdx.x;      // warp = j, lane = k
    float sv = g_sb[2][b * JK_ + tid];
    float sq = sv * sv;
    #pragma unroll
    for (int o = 16; o; o >>= 1) sq += __shfl_xor_sync(0xffffffffu, sq, o);
    out[b * JK_ + tid] = (sq / ((1.0f + sq) * sqrtf(sq + 1e-7f))) * sv;
}

extern "C" void kernel_launch(void* const* d_in, const int* in_sizes, int n_in,
                              void* d_out, int out_size) {
    const float* inp = (const float*)d_in[0];   // [64, 2048, 16]
    const float* W   = (const float*)d_in[1];   // [32, 2048, 32, 16]
    float* out = (float*)d_out;                 // [64, 32, 32]

    k_init<<<192, 1024>>>();                    // zero s0,s1,s2
    k_pad<<<1, 32>>>();                         // align ncu capture (#4) ...
    k_pad<<<1, 32>>>();                         // ... on k_uhat
    k_uhat<<<1184, 256>>>(inp, W);              // u_hat + s0 (24 warps/SM)
    k_route<<<dim3(32, 64), 256>>>(0, 0, 1, 0); // V0 -> s1
    k_route<<<dim3(32, 64), 256>>>(0, 1, 2, 1); // V0+V1 -> s2
    k_squash_final<<<64, 1024>>>(out);
}

// round 9
// speedup vs baseline: 1.3243x; 1.1066x over previous
#include <cuda_runtime.h>
#include <cuda_fp16.h>
#include <cstdint>

#define B_  64
#define N_  2048
#define I_  16
#define JK_ 1024

typedef unsigned long long ull;

// Scratch: u_hat fp16 [b][n][jk] (256 MB); three s buffers (iter 0,1,2)
__device__ __half g_uhat[(size_t)B_ * N_ * JK_];
__device__ float  g_sb[3][B_ * JK_];

// ---------------- packed fp32x2 helpers (sm_100+) ----------------
static __device__ __forceinline__ ull fma2(ull a, ull b, ull c) {
    ull d;
    asm("fma.rn.f32x2 %0, %1, %2, %3;" : "=l"(d) : "l"(a), "l"(b), "l"(c));
    return d;
}
static __device__ __forceinline__ ull add2(ull a, ull b) {
    ull d;
    asm("add.rn.f32x2 %0, %1, %2;" : "=l"(d) : "l"(a), "l"(b));
    return d;
}
static __device__ __forceinline__ float2 ull2f2(ull v) {
    float2 f;
    asm("mov.b64 {%0, %1}, %2;" : "=f"(f.x), "=f"(f.y) : "l"(v));
    return f;
}
static __device__ __forceinline__ ull packf2(float x, float y) {
    ull r;
    asm("mov.b64 %0, {%1, %2};" : "=l"(r) : "f"(x), "f"(y));
    return r;
}
static __device__ __forceinline__ ull dupf(float x) {
    ull r;
    asm("mov.b64 %0, {%1, %1};" : "=l"(r) : "f"(x));
    return r;
}
static __device__ __forceinline__ ull h2f2(unsigned int h) {
    __half2 hh = *reinterpret_cast<__half2*>(&h);
    float2 f = __half22float2(hh);
    return packf2(f.x, f.y);
}
static __device__ __forceinline__ void red4(float* p, float4 v) {
    asm volatile("red.global.add.v4.f32 [%0], {%1,%2,%3,%4};"
                 :: "l"(p), "f"(v.x), "f"(v.y), "f"(v.z), "f"(v.w) : "memory");
}

__global__ void __launch_bounds__(1024) k_init() {
    int idx = blockIdx.x * 1024 + threadIdx.x;   // grid 192 -> 196608
    (&g_sb[0][0])[idx] = 0.0f;
}

// ---------------- fused u_hat generation + iteration-0 s ----------------
// R6 version, measured 162.5us: grid 296 = 148 strips x 2 jk-halves,
// 512 thr, register s0 accumulator, double-buffered staging.
__global__ void __launch_bounds__(512, 1) k_uhat(const float* __restrict__ inp,
                                                 const float* __restrict__ W) {
    extern __shared__ float sm[];
    float* Wb0 = sm;                 // 16i x 512jk
    float* Wb1 = sm + 8192;
    float* Xs0 = sm + 16384;         // 16i x 64b
    float* Xs1 = sm + 17408;         // 72 KB

    const int tid = threadIdx.x;
    const int jkh = blockIdx.x & 1;
    const int idx = blockIdx.x >> 1;   // 0..147

    const int jkg = jkh * 512 + tid;
    const int wj = jkg >> 5, wk = jkg & 31;
    const float* wbase = W + (size_t)wj * N_ * 512 + wk * 16;
    const int xb = tid >> 3, xi = (tid & 7) * 2;
    const float* xbase = inp + (size_t)xb * N_ * 16 + xi;

    const int jkq = tid & 63;      // jk(local) = jkq*4 (+0..3) and 256+jkq*4
    const int bq  = tid >> 6;      // 8-b group

    const int total = (N_ - idx + 147) / 148;

    float4 wr0, wr1, wr2, wr3; float2 xr;
    {
        const float* ws = wbase + (size_t)idx * 512;
        wr0 = *reinterpret_cast<const float4*>(ws);
        wr1 = *reinterpret_cast<const float4*>(ws + 4);
        wr2 = *reinterpret_cast<const float4*>(ws + 8);
        wr3 = *reinterpret_cast<const float4*>(ws + 12);
        xr = *reinterpret_cast<const float2*>(xbase + (size_t)idx * 16);
        Wb0[0*512+tid]=wr0.x;  Wb0[1*512+tid]=wr0.y;  Wb0[2*512+tid]=wr0.z;  Wb0[3*512+tid]=wr0.w;
        Wb0[4*512+tid]=wr1.x;  Wb0[5*512+tid]=wr1.y;  Wb0[6*512+tid]=wr1.z;  Wb0[7*512+tid]=wr1.w;
        Wb0[8*512+tid]=wr2.x;  Wb0[9*512+tid]=wr2.y;  Wb0[10*512+tid]=wr2.z; Wb0[11*512+tid]=wr2.w;
        Wb0[12*512+tid]=wr3.x; Wb0[13*512+tid]=wr3.y; Wb0[14*512+tid]=wr3.z; Wb0[15*512+tid]=wr3.w;
        Xs0[xi * 64 + xb] = xr.x;
        Xs0[(xi + 1) * 64 + xb] = xr.y;
    }

    ull s0a[8][4];
    #pragma unroll
    for (int m = 0; m < 8; m++)
        #pragma unroll
        for (int p = 0; p < 4; p++) s0a[m][p] = 0ull;

    for (int t = 0; t < total; t++) {
        __syncthreads();
        const int ncur = idx + t * 148;
        const bool more = (t + 1 < total);
        if (more) {
            const int nn = ncur + 148;
            const float* ws = wbase + (size_t)nn * 512;
            wr0 = *reinterpret_cast<const float4*>(ws);
            wr1 = *reinterpret_cast<const float4*>(ws + 4);
            wr2 = *reinterpret_cast<const float4*>(ws + 8);
            wr3 = *reinterpret_cast<const float4*>(ws + 12);
            xr = *reinterpret_cast<const float2*>(xbase + (size_t)nn * 16);
        }
        const float* Wc = (t & 1) ? Wb1 : Wb0;
        const float* Xc = (t & 1) ? Xs1 : Xs0;

        ull acc[8][4];
        #pragma unroll
        for (int m = 0; m < 8; m++)
            #pragma unroll
            for (int p = 0; p < 4; p++) acc[m][p] = 0ull;

        #pragma unroll
        for (int i = 0; i < 16; i++) {
            float4 wa = *reinterpret_cast<const float4*>(Wc + i * 512 + jkq * 4);
            float4 wb = *reinterpret_cast<const float4*>(Wc + i * 512 + 256 + jkq * 4);
            ull wd0 = dupf(wa.x), wd1 = dupf(wa.y), wd2 = dupf(wa.z), wd3 = dupf(wa.w);
            ull wd4 = dupf(wb.x), wd5 = dupf(wb.y), wd6 = dupf(wb.z), wd7 = dupf(wb.w);
            ulonglong2 xu0 = *reinterpret_cast<const ulonglong2*>(Xc + i * 64 + bq * 8);
            ulonglong2 xu1 = *reinterpret_cast<const ulonglong2*>(Xc + i * 64 + bq * 8 + 4);
            ull xp0 = xu0.x, xp1 = xu0.y, xp2 = xu1.x, xp3 = xu1.y;
            acc[0][0]=fma2(wd0,xp0,acc[0][0]); acc[0][1]=fma2(wd0,xp1,acc[0][1]);
            acc[0][2]=fma2(wd0,xp2,acc[0][2]); acc[0][3]=fma2(wd0,xp3,acc[0][3]);
            acc[1][0]=fma2(wd1,xp0,acc[1][0]); acc[1][1]=fma2(wd1,xp1,acc[1][1]);
            acc[1][2]=fma2(wd1,xp2,acc[1][2]); acc[1][3]=fma2(wd1,xp3,acc[1][3]);
            acc[2][0]=fma2(wd2,xp0,acc[2][0]); acc[2][1]=fma2(wd2,xp1,acc[2][1]);
            acc[2][2]=fma2(wd2,xp2,acc[2][2]); acc[2][3]=fma2(wd2,xp3,acc[2][3]);
            acc[3][0]=fma2(wd3,xp0,acc[3][0]); acc[3][1]=fma2(wd3,xp1,acc[3][1]);
            acc[3][2]=fma2(wd3,xp2,acc[3][2]); acc[3][3]=fma2(wd3,xp3,acc[3][3]);
            acc[4][0]=fma2(wd4,xp0,acc[4][0]); acc[4][1]=fma2(wd4,xp1,acc[4][1]);
            acc[4][2]=fma2(wd4,xp2,acc[4][2]); acc[4][3]=fma2(wd4,xp3,acc[4][3]);
            acc[5][0]=fma2(wd5,xp0,acc[5][0]); acc[5][1]=fma2(wd5,xp1,acc[5][1]);
            acc[5][2]=fma2(wd5,xp2,acc[5][2]); acc[5][3]=fma2(wd5,xp3,acc[5][3]);
            acc[6][0]=fma2(wd6,xp0,acc[6][0]); acc[6][1]=fma2(wd6,xp1,acc[6][1]);
            acc[6][2]=fma2(wd6,xp2,acc[6][2]); acc[6][3]=fma2(wd6,xp3,acc[6][3]);
            acc[7][0]=fma2(wd7,xp0,acc[7][0]); acc[7][1]=fma2(wd7,xp1,acc[7][1]);
            acc[7][2]=fma2(wd7,xp2,acc[7][2]); acc[7][3]=fma2(wd7,xp3,acc[7][3]);
        }

        if (more) {
            float* Wn = (t & 1) ? Wb0 : Wb1;
            float* Xn = (t & 1) ? Xs0 : Xs1;
            Wn[0*512+tid]=wr0.x;  Wn[1*512+tid]=wr0.y;  Wn[2*512+tid]=wr0.z;  Wn[3*512+tid]=wr0.w;
            Wn[4*512+tid]=wr1.x;  Wn[5*512+tid]=wr1.y;  Wn[6*512+tid]=wr1.z;  Wn[7*512+tid]=wr1.w;
            Wn[8*512+tid]=wr2.x;  Wn[9*512+tid]=wr2.y;  Wn[10*512+tid]=wr2.z; Wn[11*512+tid]=wr2.w;
            Wn[12*512+tid]=wr3.x; Wn[13*512+tid]=wr3.y; Wn[14*512+tid]=wr3.z; Wn[15*512+tid]=wr3.w;
            Xn[xi * 64 + xb] = xr.x;
            Xn[(xi + 1) * 64 + xb] = xr.y;
        }

        // epilogue: s0 += acc; store u_hat fp16
        #pragma unroll
        for (int m = 0; m < 8; m++)
            #pragma unroll
            for (int p = 0; p < 4; p++) s0a[m][p] = add2(s0a[m][p], acc[m][p]);

        #pragma unroll
        for (int p = 0; p < 4; p++) {
            float2 a0 = ull2f2(acc[0][p]), a1 = ull2f2(acc[1][p]);
            float2 a2 = ull2f2(acc[2][p]), a3 = ull2f2(acc[3][p]);
            float2 a4 = ull2f2(acc[4][p]), a5 = ull2f2(acc[5][p]);
            float2 a6 = ull2f2(acc[6][p]), a7 = ull2f2(acc[7][p]);
            #pragma unroll
            for (int e = 0; e < 2; e++) {
                const int bg = bq * 8 + 2 * p + e;
                float f0 = e ? a0.y : a0.x, f1 = e ? a1.y : a1.x;
                float f2 = e ? a2.y : a2.x, f3 = e ? a3.y : a3.x;
                float f4 = e ? a4.y : a4.x, f5 = e ? a5.y : a5.x;
                float f6 = e ? a6.y : a6.x, f7 = e ? a7.y : a7.x;

                __half2 hA0 = __floats2half2_rn(f0, f1), hA1 = __floats2half2_rn(f2, f3);
                __half2 hB0 = __floats2half2_rn(f4, f5), hB1 = __floats2half2_rn(f6, f7);
                __half* up = g_uhat + ((size_t)bg * N_ + ncur) * JK_ + jkh * 512;
                uint2 vA, vB;
                vA.x = *reinterpret_cast<unsigned int*>(&hA0);
                vA.y = *reinterpret_cast<unsigned int*>(&hA1);
                vB.x = *reinterpret_cast<unsigned int*>(&hB0);
                vB.y = *reinterpret_cast<unsigned int*>(&hB1);
                *reinterpret_cast<uint2*>(up + jkq * 4) = vA;
                *reinterpret_cast<uint2*>(up + 256 + jkq * 4) = vB;
            }
        }
    }

    // flush register s0 (scaled by 1/32)
    #pragma unroll
    for (int p = 0; p < 4; p++) {
        float2 a0 = ull2f2(s0a[0][p]), a1 = ull2f2(s0a[1][p]);
        float2 a2 = ull2f2(s0a[2][p]), a3 = ull2f2(s0a[3][p]);
        float2 a4 = ull2f2(s0a[4][p]), a5 = ull2f2(s0a[5][p]);
        float2 a6 = ull2f2(s0a[6][p]), a7 = ull2f2(s0a[7][p]);
        #pragma unroll
        for (int e = 0; e < 2; e++) {
            const int bg = bq * 8 + 2 * p + e;
            float f0 = (e ? a0.y : a0.x) * 0.03125f, f1 = (e ? a1.y : a1.x) * 0.03125f;
            float f2 = (e ? a2.y : a2.x) * 0.03125f, f3 = (e ? a3.y : a3.x) * 0.03125f;
            float f4 = (e ? a4.y : a4.x) * 0.03125f, f5 = (e ? a5.y : a5.x) * 0.03125f;
            float f6 = (e ? a6.y : a6.x) * 0.03125f, f7 = (e ? a7.y : a7.x) * 0.03125f;
            float* dst = &g_sb[0][bg * JK_ + jkh * 512];
            red4(dst + jkq * 4,       make_float4(f0, f1, f2, f3));
            red4(dst + 256 + jkq * 4, make_float4(f4, f5, f6, f7));
        }
    }
}

// ---------------- fused squash + routing pass (R5 version, 67us measured) ----
// Warp strip widened 8 -> 16 n (grid x 32 -> 16): same math, less V-build
// overhead and half the red4 flushes.
__global__ void __launch_bounds__(256, 2)
k_route(int ia, int ib, int io, int two) {
    __shared__ float V_sm[1024];
    __shared__ float ws[8 * 1024];     // per-warp s partials

    const float* sa = g_sb[ia];
    const float* sb = g_sb[ib];
    float* sout = g_sb[io];

    const int chunk = blockIdx.x;      // 0..15
    const int b     = blockIdx.y;      // 0..63
    const int tid   = threadIdx.x;     // 256
    const int warp  = tid >> 5;
    const int lane  = tid & 31;

    // --- build V[j][k] = squash(sa) [+ squash(sb)] ---
    #pragma unroll
    for (int r = 0; r < 4; r++) {
        int j = warp * 4 + r;
        float va = sa[b * JK_ + j * 32 + lane];
        float sq = va * va;
        #pragma unroll
        for (int o = 16; o; o >>= 1) sq += __shfl_xor_sync(0xffffffffu, sq, o);
        float val = (sq / ((1.0f + sq) * sqrtf(sq + 1e-7f))) * va;
        if (two) {
            float vb = sb[b * JK_ + j * 32 + lane];
            float sqb = vb * vb;
            #pragma unroll
            for (int o = 16; o; o >>= 1) sqb += __shfl_xor_sync(0xffffffffu, sqb, o);
            val += (sqb / ((1.0f + sqb) * sqrtf(sqb + 1e-7f))) * vb;
        }
        V_sm[j * 32 + lane] = val;
    }
    __syncthreads();

    // lane's V slice: for q, jk = q*256 + lane*8 .. +7
    ull vq[4][4];
    #pragma unroll
    for (int q = 0; q < 4; q++) {
        float4 a = *reinterpret_cast<const float4*>(V_sm + q * 256 + lane * 8);
        float4 c = *reinterpret_cast<const float4*>(V_sm + q * 256 + lane * 8 + 4);
        vq[q][0] = packf2(a.x, a.y); vq[q][1] = packf2(a.z, a.w);
        vq[q][2] = packf2(c.x, c.y); vq[q][3] = packf2(c.z, c.w);
    }

    ull sacc[4][4];
    #pragma unroll
    for (int q = 0; q < 4; q++)
        #pragma unroll
        for (int m = 0; m < 4; m++) sacc[q][m] = 0ull;

    const char* row0 = reinterpret_cast<const char*>(
        g_uhat + ((size_t)b * N_ + (size_t)(chunk * 128 + warp * 16)) * JK_) + lane * 16;

    uint4 cur0, cur1, cur2, cur3, nxt0, nxt1, nxt2, nxt3;
    cur0 = *reinterpret_cast<const uint4*>(row0);
    cur1 = *reinterpret_cast<const uint4*>(row0 + 512);
    cur2 = *reinterpret_cast<const uint4*>(row0 + 1024);
    cur3 = *reinterpret_cast<const uint4*>(row0 + 1536);

    #pragma unroll
    for (int t = 0; t < 16; t++) {
        if (t < 15) {
            const char* rn = row0 + (size_t)(t + 1) * 2048;
            nxt0 = *reinterpret_cast<const uint4*>(rn);
            nxt1 = *reinterpret_cast<const uint4*>(rn + 512);
            nxt2 = *reinterpret_cast<const uint4*>(rn + 1024);
            nxt3 = *reinterpret_cast<const uint4*>(rn + 1536);
        }
        uint4 c4[4] = {cur0, cur1, cur2, cur3};
        float e[4];
        #pragma unroll
        for (int q = 0; q < 4; q++) {
            ull u0 = h2f2(c4[q].x), u1 = h2f2(c4[q].y);
            ull u2 = h2f2(c4[q].z), u3 = h2f2(c4[q].w);
            ull d = fma2(u0, vq[q][0], fma2(u1, vq[q][1],
                    fma2(u2, vq[q][2], fma2(u3, vq[q][3], 0ull))));
            float2 df = ull2f2(d);
            float bp = df.x + df.y;
            bp += __shfl_xor_sync(0xffffffffu, bp, 1);
            bp += __shfl_xor_sync(0xffffffffu, bp, 2);
            e[q] = __expf(bp);          // logits bounded; no max needed
        }
        float tot = e[0] + e[1] + e[2] + e[3];
        tot += __shfl_xor_sync(0xffffffffu, tot, 4);
        tot += __shfl_xor_sync(0xffffffffu, tot, 8);
        tot += __shfl_xor_sync(0xffffffffu, tot, 16);
        float inv = __fdividef(1.0f, tot);
        #pragma unroll
        for (int q = 0; q < 4; q++) {
            ull cq2 = dupf(e[q] * inv);
            ull u0 = h2f2(c4[q].x), u1 = h2f2(c4[q].y);
            ull u2 = h2f2(c4[q].z), u3 = h2f2(c4[q].w);
            sacc[q][0] = fma2(cq2, u0, sacc[q][0]);
            sacc[q][1] = fma2(cq2, u1, sacc[q][1]);
            sacc[q][2] = fma2(cq2, u2, sacc[q][2]);
            sacc[q][3] = fma2(cq2, u3, sacc[q][3]);
        }
        if (t < 15) { cur0 = nxt0; cur1 = nxt1; cur2 = nxt2; cur3 = nxt3; }
    }

    // per-warp private store (no atomics)
    #pragma unroll
    for (int q = 0; q < 4; q++) {
        float2 f0 = ull2f2(sacc[q][0]), f1 = ull2f2(sacc[q][1]);
        float2 f2 = ull2f2(sacc[q][2]), f3 = ull2f2(sacc[q][3]);
        float* wp = ws + warp * 1024 + q * 256 + lane * 8;
        *reinterpret_cast<float4*>(wp)     = make_float4(f0.x, f0.y, f1.x, f1.y);
        *reinterpret_cast<float4*>(wp + 4) = make_float4(f2.x, f2.y, f3.x, f3.y);
    }
    __syncthreads();

    // cross-warp tree reduce + global flush
    float4 a = *reinterpret_cast<const float4*>(ws + tid * 4);
    #pragma unroll
    for (int w = 1; w < 8; w++) {
        float4 x = *reinterpret_cast<const float4*>(ws + w * 1024 + tid * 4);
        a.x += x.x; a.y += x.y; a.z += x.z; a.w += x.w;
    }
    red4(sout + b * JK_ + tid * 4, a);
}

// ---------------- final squash ----------------
__global__ void __launch_bounds__(1024) k_squash_final(float* __restrict__ out) {
    const int b   = blockIdx.x;
    const int tid = threadIdx.x;      // warp = j, lane = k
    float sv = g_sb[2][b * JK_ + tid];
    float sq = sv * sv;
    #pragma unroll
    for (int o = 16; o; o >>= 1) sq += __shfl_xor_sync(0xffffffffu, sq, o);
    out[b * JK_ + tid] = (sq / ((1.0f + sq) * sqrtf(sq + 1e-7f))) * sv;
}

extern "C" void kernel_launch(void* const* d_in, const int* in_sizes, int n_in,
                              void* d_out, int out_size) {
    const float* inp = (const float*)d_in[0];   // [64, 2048, 16]
    const float* W   = (const float*)d_in[1];   // [32, 2048, 32, 16]
    float* out = (float*)d_out;                 // [64, 32, 32]

    cudaFuncSetAttribute(k_uhat, cudaFuncAttributeMaxDynamicSharedMemorySize, 73728);

    k_init<<<192, 1024>>>();                    // zero s0,s1,s2
    k_uhat<<<296, 512, 73728>>>(inp, W);        // u_hat + s0 (measured 162.5us)
    k_route<<<dim3(16, 64), 256>>>(0, 0, 1, 0); // V0 -> s1
    k_route<<<dim3(16, 64), 256>>>(0, 1, 2, 1); // V0+V1 -> s2  (ncu #4)
    k_squash_final<<<64, 1024>>>(out);
}

// round 10
// speedup vs baseline: 1.3522x; 1.0211x over previous
#include <cuda_runtime.h>
#include <cuda_fp16.h>
#include <cstdint>

#define B_  64
#define N_  2048
#define I_  16
#define JK_ 1024

typedef unsigned long long ull;

// Scratch: u_hat fp16 [b][n][jk] (256 MB); three s buffers (iter 0,1,2)
__device__ __half g_uhat[(size_t)B_ * N_ * JK_];
__device__ float  g_sb[3][B_ * JK_];

// ---------------- packed fp32x2 helpers (sm_100+) ----------------
static __device__ __forceinline__ ull fma2(ull a, ull b, ull c) {
    ull d;
    asm("fma.rn.f32x2 %0, %1, %2, %3;" : "=l"(d) : "l"(a), "l"(b), "l"(c));
    return d;
}
static __device__ __forceinline__ ull add2(ull a, ull b) {
    ull d;
    asm("add.rn.f32x2 %0, %1, %2;" : "=l"(d) : "l"(a), "l"(b));
    return d;
}
static __device__ __forceinline__ float2 ull2f2(ull v) {
    float2 f;
    asm("mov.b64 {%0, %1}, %2;" : "=f"(f.x), "=f"(f.y) : "l"(v));
    return f;
}
static __device__ __forceinline__ ull packf2(float x, float y) {
    ull r;
    asm("mov.b64 %0, {%1, %2};" : "=l"(r) : "f"(x), "f"(y));
    return r;
}
static __device__ __forceinline__ ull dupf(float x) {
    ull r;
    asm("mov.b64 %0, {%1, %1};" : "=l"(r) : "f"(x));
    return r;
}
static __device__ __forceinline__ ull h2f2(unsigned int h) {
    __half2 hh = *reinterpret_cast<__half2*>(&h);
    float2 f = __half22float2(hh);
    return packf2(f.x, f.y);
}
static __device__ __forceinline__ void red4(float* p, float4 v) {
    asm volatile("red.global.add.v4.f32 [%0], {%1,%2,%3,%4};"
                 :: "l"(p), "f"(v.x), "f"(v.y), "f"(v.z), "f"(v.w) : "memory");
}

__global__ void __launch_bounds__(1024) k_init() {
    int idx = blockIdx.x * 1024 + threadIdx.x;   // grid 192 -> 196608
    (&g_sb[0][0])[idx] = 0.0f;
}

// ---------------- fused u_hat generation + iteration-0 s ----------------
// 256-thread CTAs (2 CTAs/SM), tile = 64b x 256jk; grid 592 = 148 strips x
// 4 jk-quarters. Same inner-loop shape as the measured R6 kernel, but the
// second resident CTA hides barrier/staging bubbles.
__global__ void __launch_bounds__(256, 2) k_uhat(const float* __restrict__ inp,
                                                 const float* __restrict__ W) {
    __shared__ float Wb[2][16 * 256];   // [buf][i][jk_local]  2x16KB
    __shared__ float Xs[2][16 * 64];    // [buf][i][b]         2x4KB

    const int tid = threadIdx.x;
    const int jkQ = blockIdx.x & 3;     // jk quarter
    const int idx = blockIdx.x >> 2;    // n-strip 0..147

    // staging: thread stages jk row 'tid' (16 i) and 4 X floats
    const int jkg = jkQ * 256 + tid;
    const int wj = jkg >> 5, wk = jkg & 31;
    const float* wbase = W + (size_t)wj * N_ * 512 + wk * 16;
    const int xb = tid & 63, xi = (tid >> 6) * 4;
    const float* xbase = inp + (size_t)xb * N_ * 16 + xi;

    const int jkq = tid & 31;      // jk quads: jkq*4 and 128+jkq*4
    const int bq  = tid >> 5;      // 8-b group (0..7)

    const int total = (N_ - idx + 147) / 148;

    float4 wr0, wr1, wr2, wr3, xr;
    {
        const float* ws = wbase + (size_t)idx * 512;
        wr0 = *reinterpret_cast<const float4*>(ws);
        wr1 = *reinterpret_cast<const float4*>(ws + 4);
        wr2 = *reinterpret_cast<const float4*>(ws + 8);
        wr3 = *reinterpret_cast<const float4*>(ws + 12);
        xr  = *reinterpret_cast<const float4*>(xbase + (size_t)idx * 16);
        Wb[0][0*256+tid]=wr0.x;  Wb[0][1*256+tid]=wr0.y;  Wb[0][2*256+tid]=wr0.z;  Wb[0][3*256+tid]=wr0.w;
        Wb[0][4*256+tid]=wr1.x;  Wb[0][5*256+tid]=wr1.y;  Wb[0][6*256+tid]=wr1.z;  Wb[0][7*256+tid]=wr1.w;
        Wb[0][8*256+tid]=wr2.x;  Wb[0][9*256+tid]=wr2.y;  Wb[0][10*256+tid]=wr2.z; Wb[0][11*256+tid]=wr2.w;
        Wb[0][12*256+tid]=wr3.x; Wb[0][13*256+tid]=wr3.y; Wb[0][14*256+tid]=wr3.z; Wb[0][15*256+tid]=wr3.w;
        Xs[0][(xi + 0) * 64 + xb] = xr.x;
        Xs[0][(xi + 1) * 64 + xb] = xr.y;
        Xs[0][(xi + 2) * 64 + xb] = xr.z;
        Xs[0][(xi + 3) * 64 + xb] = xr.w;
    }

    ull s0a[8][4];
    #pragma unroll
    for (int m = 0; m < 8; m++)
        #pragma unroll
        for (int p = 0; p < 4; p++) s0a[m][p] = 0ull;

    for (int t = 0; t < total; t++) {
        __syncthreads();
        const int ncur = idx + t * 148;
        const bool more = (t + 1 < total);
        if (more) {
            const int nn = ncur + 148;
            const float* ws = wbase + (size_t)nn * 512;
            wr0 = *reinterpret_cast<const float4*>(ws);
            wr1 = *reinterpret_cast<const float4*>(ws + 4);
            wr2 = *reinterpret_cast<const float4*>(ws + 8);
            wr3 = *reinterpret_cast<const float4*>(ws + 12);
            xr  = *reinterpret_cast<const float4*>(xbase + (size_t)nn * 16);
        }
        const float* Wc = Wb[t & 1];
        const float* Xc = Xs[t & 1];

        ull acc[8][4];
        #pragma unroll
        for (int m = 0; m < 8; m++)
            #pragma unroll
            for (int p = 0; p < 4; p++) acc[m][p] = 0ull;

        #pragma unroll
        for (int i = 0; i < 16; i++) {
            float4 wa = *reinterpret_cast<const float4*>(Wc + i * 256 + jkq * 4);
            float4 wb = *reinterpret_cast<const float4*>(Wc + i * 256 + 128 + jkq * 4);
            ull wd0 = dupf(wa.x), wd1 = dupf(wa.y), wd2 = dupf(wa.z), wd3 = dupf(wa.w);
            ull wd4 = dupf(wb.x), wd5 = dupf(wb.y), wd6 = dupf(wb.z), wd7 = dupf(wb.w);
            ulonglong2 xu0 = *reinterpret_cast<const ulonglong2*>(Xc + i * 64 + bq * 8);
            ulonglong2 xu1 = *reinterpret_cast<const ulonglong2*>(Xc + i * 64 + bq * 8 + 4);
            ull xp0 = xu0.x, xp1 = xu0.y, xp2 = xu1.x, xp3 = xu1.y;
            acc[0][0]=fma2(wd0,xp0,acc[0][0]); acc[0][1]=fma2(wd0,xp1,acc[0][1]);
            acc[0][2]=fma2(wd0,xp2,acc[0][2]); acc[0][3]=fma2(wd0,xp3,acc[0][3]);
            acc[1][0]=fma2(wd1,xp0,acc[1][0]); acc[1][1]=fma2(wd1,xp1,acc[1][1]);
            acc[1][2]=fma2(wd1,xp2,acc[1][2]); acc[1][3]=fma2(wd1,xp3,acc[1][3]);
            acc[2][0]=fma2(wd2,xp0,acc[2][0]); acc[2][1]=fma2(wd2,xp1,acc[2][1]);
            acc[2][2]=fma2(wd2,xp2,acc[2][2]); acc[2][3]=fma2(wd2,xp3,acc[2][3]);
            acc[3][0]=fma2(wd3,xp0,acc[3][0]); acc[3][1]=fma2(wd3,xp1,acc[3][1]);
            acc[3][2]=fma2(wd3,xp2,acc[3][2]); acc[3][3]=fma2(wd3,xp3,acc[3][3]);
            acc[4][0]=fma2(wd4,xp0,acc[4][0]); acc[4][1]=fma2(wd4,xp1,acc[4][1]);
            acc[4][2]=fma2(wd4,xp2,acc[4][2]); acc[4][3]=fma2(wd4,xp3,acc[4][3]);
            acc[5][0]=fma2(wd5,xp0,acc[5][0]); acc[5][1]=fma2(wd5,xp1,acc[5][1]);
            acc[5][2]=fma2(wd5,xp2,acc[5][2]); acc[5][3]=fma2(wd5,xp3,acc[5][3]);
            acc[6][0]=fma2(wd6,xp0,acc[6][0]); acc[6][1]=fma2(wd6,xp1,acc[6][1]);
            acc[6][2]=fma2(wd6,xp2,acc[6][2]); acc[6][3]=fma2(wd6,xp3,acc[6][3]);
            acc[7][0]=fma2(wd7,xp0,acc[7][0]); acc[7][1]=fma2(wd7,xp1,acc[7][1]);
            acc[7][2]=fma2(wd7,xp2,acc[7][2]); acc[7][3]=fma2(wd7,xp3,acc[7][3]);
        }

        if (more) {
            float* Wn = Wb[(t + 1) & 1];
            float* Xn = Xs[(t + 1) & 1];
            Wn[0*256+tid]=wr0.x;  Wn[1*256+tid]=wr0.y;  Wn[2*256+tid]=wr0.z;  Wn[3*256+tid]=wr0.w;
            Wn[4*256+tid]=wr1.x;  Wn[5*256+tid]=wr1.y;  Wn[6*256+tid]=wr1.z;  Wn[7*256+tid]=wr1.w;
            Wn[8*256+tid]=wr2.x;  Wn[9*256+tid]=wr2.y;  Wn[10*256+tid]=wr2.z; Wn[11*256+tid]=wr2.w;
            Wn[12*256+tid]=wr3.x; Wn[13*256+tid]=wr3.y; Wn[14*256+tid]=wr3.z; Wn[15*256+tid]=wr3.w;
            Xn[(xi + 0) * 64 + xb] = xr.x;
            Xn[(xi + 1) * 64 + xb] = xr.y;
            Xn[(xi + 2) * 64 + xb] = xr.z;
            Xn[(xi + 3) * 64 + xb] = xr.w;
        }

        // epilogue: s0 += acc; store u_hat fp16
        #pragma unroll
        for (int m = 0; m < 8; m++)
            #pragma unroll
            for (int p = 0; p < 4; p++) s0a[m][p] = add2(s0a[m][p], acc[m][p]);

        #pragma unroll
        for (int p = 0; p < 4; p++) {
            float2 a0 = ull2f2(acc[0][p]), a1 = ull2f2(acc[1][p]);
            float2 a2 = ull2f2(acc[2][p]), a3 = ull2f2(acc[3][p]);
            float2 a4 = ull2f2(acc[4][p]), a5 = ull2f2(acc[5][p]);
            float2 a6 = ull2f2(acc[6][p]), a7 = ull2f2(acc[7][p]);
            #pragma unroll
            for (int e = 0; e < 2; e++) {
                const int bg = bq * 8 + 2 * p + e;
                float f0 = e ? a0.y : a0.x, f1 = e ? a1.y : a1.x;
                float f2 = e ? a2.y : a2.x, f3 = e ? a3.y : a3.x;
                float f4 = e ? a4.y : a4.x, f5 = e ? a5.y : a5.x;
                float f6 = e ? a6.y : a6.x, f7 = e ? a7.y : a7.x;

                __half2 hA0 = __floats2half2_rn(f0, f1), hA1 = __floats2half2_rn(f2, f3);
                __half2 hB0 = __floats2half2_rn(f4, f5), hB1 = __floats2half2_rn(f6, f7);
                __half* up = g_uhat + ((size_t)bg * N_ + ncur) * JK_ + jkQ * 256;
                uint2 vA, vB;
                vA.x = *reinterpret_cast<unsigned int*>(&hA0);
                vA.y = *reinterpret_cast<unsigned int*>(&hA1);
                vB.x = *reinterpret_cast<unsigned int*>(&hB0);
                vB.y = *reinterpret_cast<unsigned int*>(&hB1);
                *reinterpret_cast<uint2*>(up + jkq * 4) = vA;
                *reinterpret_cast<uint2*>(up + 128 + jkq * 4) = vB;
            }
        }
    }

    // flush register s0 (scaled by 1/32)
    #pragma unroll
    for (int p = 0; p < 4; p++) {
        float2 a0 = ull2f2(s0a[0][p]), a1 = ull2f2(s0a[1][p]);
        float2 a2 = ull2f2(s0a[2][p]), a3 = ull2f2(s0a[3][p]);
        float2 a4 = ull2f2(s0a[4][p]), a5 = ull2f2(s0a[5][p]);
        float2 a6 = ull2f2(s0a[6][p]), a7 = ull2f2(s0a[7][p]);
        #pragma unroll
        for (int e = 0; e < 2; e++) {
            const int bg = bq * 8 + 2 * p + e;
            float f0 = (e ? a0.y : a0.x) * 0.03125f, f1 = (e ? a1.y : a1.x) * 0.03125f;
            float f2 = (e ? a2.y : a2.x) * 0.03125f, f3 = (e ? a3.y : a3.x) * 0.03125f;
            float f4 = (e ? a4.y : a4.x) * 0.03125f, f5 = (e ? a5.y : a5.x) * 0.03125f;
            float f6 = (e ? a6.y : a6.x) * 0.03125f, f7 = (e ? a7.y : a7.x) * 0.03125f;
            float* dst = &g_sb[0][bg * JK_ + jkQ * 256];
            red4(dst + jkq * 4,       make_float4(f0, f1, f2, f3));
            red4(dst + 128 + jkq * 4, make_float4(f4, f5, f6, f7));
        }
    }
}

// ---------------- fused squash + routing pass (exact R5 version, 67us) ------
__global__ void __launch_bounds__(256, 2)
k_route(int ia, int ib, int io, int two) {
    __shared__ float V_sm[1024];
    __shared__ float ws[8 * 1024];     // per-warp s partials

    const float* sa = g_sb[ia];
    const float* sb = g_sb[ib];
    float* sout = g_sb[io];

    const int chunk = blockIdx.x;      // 0..31
    const int b     = blockIdx.y;      // 0..63
    const int tid   = threadIdx.x;     // 256
    const int warp  = tid >> 5;
    const int lane  = tid & 31;

    // --- build V[j][k] = squash(sa) [+ squash(sb)] ---
    #pragma unroll
    for (int r = 0; r < 4; r++) {
        int j = warp * 4 + r;
        float va = sa[b * JK_ + j * 32 + lane];
        float sq = va * va;
        #pragma unroll
        for (int o = 16; o; o >>= 1) sq += __shfl_xor_sync(0xffffffffu, sq, o);
        float val = (sq / ((1.0f + sq) * sqrtf(sq + 1e-7f))) * va;
        if (two) {
            float vb = sb[b * JK_ + j * 32 + lane];
            float sqb = vb * vb;
            #pragma unroll
            for (int o = 16; o; o >>= 1) sqb += __shfl_xor_sync(0xffffffffu, sqb, o);
            val += (sqb / ((1.0f + sqb) * sqrtf(sqb + 1e-7f))) * vb;
        }
        V_sm[j * 32 + lane] = val;
    }
    __syncthreads();

    // lane's V slice: for q, jk = q*256 + lane*8 .. +7
    ull vq[4][4];
    #pragma unroll
    for (int q = 0; q < 4; q++) {
        float4 a = *reinterpret_cast<const float4*>(V_sm + q * 256 + lane * 8);
        float4 c = *reinterpret_cast<const float4*>(V_sm + q * 256 + lane * 8 + 4);
        vq[q][0] = packf2(a.x, a.y); vq[q][1] = packf2(a.z, a.w);
        vq[q][2] = packf2(c.x, c.y); vq[q][3] = packf2(c.z, c.w);
    }

    ull sacc[4][4];
    #pragma unroll
    for (int q = 0; q < 4; q++)
        #pragma unroll
        for (int m = 0; m < 4; m++) sacc[q][m] = 0ull;

    const char* row0 = reinterpret_cast<const char*>(
        g_uhat + ((size_t)b * N_ + (size_t)(chunk * 64 + warp * 8)) * JK_) + lane * 16;

    uint4 cur0, cur1, cur2, cur3, nxt0, nxt1, nxt2, nxt3;
    cur0 = *reinterpret_cast<const uint4*>(row0);
    cur1 = *reinterpret_cast<const uint4*>(row0 + 512);
    cur2 = *reinterpret_cast<const uint4*>(row0 + 1024);
    cur3 = *reinterpret_cast<const uint4*>(row0 + 1536);

    #pragma unroll
    for (int t = 0; t < 8; t++) {
        if (t < 7) {
            const char* rn = row0 + (size_t)(t + 1) * 2048;
            nxt0 = *reinterpret_cast<const uint4*>(rn);
            nxt1 = *reinterpret_cast<const uint4*>(rn + 512);
            nxt2 = *reinterpret_cast<const uint4*>(rn + 1024);
            nxt3 = *reinterpret_cast<const uint4*>(rn + 1536);
        }
        uint4 c4[4] = {cur0, cur1, cur2, cur3};
        float e[4];
        #pragma unroll
        for (int q = 0; q < 4; q++) {
            ull u0 = h2f2(c4[q].x), u1 = h2f2(c4[q].y);
            ull u2 = h2f2(c4[q].z), u3 = h2f2(c4[q].w);
            ull d = fma2(u0, vq[q][0], fma2(u1, vq[q][1],
                    fma2(u2, vq[q][2], fma2(u3, vq[q][3], 0ull))));
            float2 df = ull2f2(d);
            float bp = df.x + df.y;
            bp += __shfl_xor_sync(0xffffffffu, bp, 1);
            bp += __shfl_xor_sync(0xffffffffu, bp, 2);
            e[q] = __expf(bp);          // logits bounded; no max needed
        }
        float tot = e[0] + e[1] + e[2] + e[3];
        tot += __shfl_xor_sync(0xffffffffu, tot, 4);
        tot += __shfl_xor_sync(0xffffffffu, tot, 8);
        tot += __shfl_xor_sync(0xffffffffu, tot, 16);
        float inv = __fdividef(1.0f, tot);
        #pragma unroll
        for (int q = 0; q < 4; q++) {
            ull cq2 = dupf(e[q] * inv);
            ull u0 = h2f2(c4[q].x), u1 = h2f2(c4[q].y);
            ull u2 = h2f2(c4[q].z), u3 = h2f2(c4[q].w);
            sacc[q][0] = fma2(cq2, u0, sacc[q][0]);
            sacc[q][1] = fma2(cq2, u1, sacc[q][1]);
            sacc[q][2] = fma2(cq2, u2, sacc[q][2]);
            sacc[q][3] = fma2(cq2, u3, sacc[q][3]);
        }
        if (t < 7) { cur0 = nxt0; cur1 = nxt1; cur2 = nxt2; cur3 = nxt3; }
    }

    // per-warp private store (no atomics)
    #pragma unroll
    for (int q = 0; q < 4; q++) {
        float2 f0 = ull2f2(sacc[q][0]), f1 = ull2f2(sacc[q][1]);
        float2 f2 = ull2f2(sacc[q][2]), f3 = ull2f2(sacc[q][3]);
        float* wp = ws + warp * 1024 + q * 256 + lane * 8;
        *reinterpret_cast<float4*>(wp)     = make_float4(f0.x, f0.y, f1.x, f1.y);
        *reinterpret_cast<float4*>(wp + 4) = make_float4(f2.x, f2.y, f3.x, f3.y);
    }
    __syncthreads();

    // cross-warp tree reduce + global flush
    float4 a = *reinterpret_cast<const float4*>(ws + tid * 4);
    #pragma unroll
    for (int w = 1; w < 8; w++) {
        float4 x = *reinterpret_cast<const float4*>(ws + w * 1024 + tid * 4);
        a.x += x.x; a.y += x.y; a.z += x.z; a.w += x.w;
    }
    red4(sout + b * JK_ + tid * 4, a);
}

// ---------------- final squash ----------------
__global__ void __launch_bounds__(1024) k_squash_final(float* __restrict__ out) {
    const int b   = blockIdx.x;
    const int tid = threadIdx.x;      // warp = j, lane = k
    float sv = g_sb[2][b * JK_ + tid];
    float sq = sv * sv;
    #pragma unroll
    for (int o = 16; o; o >>= 1) sq += __shfl_xor_sync(0xffffffffu, sq, o);
    out[b * JK_ + tid] = (sq / ((1.0f + sq) * sqrtf(sq + 1e-7f))) * sv;
}

extern "C" void kernel_launch(void* const* d_in, const int* in_sizes, int n_in,
                              void* d_out, int out_size) {
    const float* inp = (const float*)d_in[0];   // [64, 2048, 16]
    const float* W   = (const float*)d_in[1];   // [32, 2048, 32, 16]
    float* out = (float*)d_out;                 // [64, 32, 32]

    k_init<<<192, 1024>>>();                    // zero s0,s1,s2
    k_uhat<<<592, 256>>>(inp, W);               // u_hat + s0 (2 CTAs/SM)
    k_route<<<dim3(32, 64), 256>>>(0, 0, 1, 0); // V0 -> s1   (ncu #4)
    k_route<<<dim3(32, 64), 256>>>(0, 1, 2, 1); // V0+V1 -> s2
    k_squash_final<<<64, 1024>>>(out);
}

// round 11
// speedup vs baseline: 1.3729x; 1.0153x over previous
#include <cuda_runtime.h>
#include <cuda_fp16.h>
#include <cstdint>

#define B_  64
#define N_  2048
#define I_  16
#define JK_ 1024

typedef unsigned long long ull;

// Scratch: u_hat fp16 [b][n][jk] (256 MB); three s buffers (iter 0,1,2)
__device__ __half g_uhat[(size_t)B_ * N_ * JK_];
__device__ float  g_sb[3][B_ * JK_];

// ---------------- packed fp32x2 helpers (sm_100+) ----------------
static __device__ __forceinline__ ull fma2(ull a, ull b, ull c) {
    ull d;
    asm("fma.rn.f32x2 %0, %1, %2, %3;" : "=l"(d) : "l"(a), "l"(b), "l"(c));
    return d;
}
static __device__ __forceinline__ ull add2(ull a, ull b) {
    ull d;
    asm("add.rn.f32x2 %0, %1, %2;" : "=l"(d) : "l"(a), "l"(b));
    return d;
}
static __device__ __forceinline__ float2 ull2f2(ull v) {
    float2 f;
    asm("mov.b64 {%0, %1}, %2;" : "=f"(f.x), "=f"(f.y) : "l"(v));
    return f;
}
static __device__ __forceinline__ ull packf2(float x, float y) {
    ull r;
    asm("mov.b64 %0, {%1, %2};" : "=l"(r) : "f"(x), "f"(y));
    return r;
}
static __device__ __forceinline__ ull dupf(float x) {
    ull r;
    asm("mov.b64 %0, {%1, %1};" : "=l"(r) : "f"(x));
    return r;
}
static __device__ __forceinline__ ull h2f2(unsigned int h) {
    __half2 hh = *reinterpret_cast<__half2*>(&h);
    float2 f = __half22float2(hh);
    return packf2(f.x, f.y);
}
static __device__ __forceinline__ void red4(float* p, float4 v) {
    asm volatile("red.global.add.v4.f32 [%0], {%1,%2,%3,%4};"
                 :: "l"(p), "f"(v.x), "f"(v.y), "f"(v.z), "f"(v.w) : "memory");
}
static __device__ __forceinline__ uint32_t smem_addr_u32(const void* p) {
    uint32_t a;
    asm("{ .reg .u64 t; cvta.to.shared.u64 t, %1; cvt.u32.u64 %0, t; }"
        : "=r"(a) : "l"(p));
    return a;
}
// volatile 128-bit shared load as two packed f32x2 words (prevents hoist/CSE)
static __device__ __forceinline__ void lds_v2u64(ull& x, ull& y, uint32_t addr) {
    asm volatile("ld.shared.v2.u64 {%0,%1}, [%2];" : "=l"(x), "=l"(y) : "r"(addr));
}

__global__ void __launch_bounds__(1024) k_init() {
    int idx = blockIdx.x * 1024 + threadIdx.x;   // grid 192 -> 196608
    (&g_sb[0][0])[idx] = 0.0f;
}

// ---------------- fused u_hat generation + iteration-0 s ----------------
// (R10 version, 2 CTAs/SM; est ~126us)
__global__ void __launch_bounds__(256, 2) k_uhat(const float* __restrict__ inp,
                                                 const float* __restrict__ W) {
    __shared__ float Wb[2][16 * 256];   // [buf][i][jk_local]  2x16KB
    __shared__ float Xs[2][16 * 64];    // [buf][i][b]         2x4KB

    const int tid = threadIdx.x;
    const int jkQ = blockIdx.x & 3;     // jk quarter
    const int idx = blockIdx.x >> 2;    // n-strip 0..147

    const int jkg = jkQ * 256 + tid;
    const int wj = jkg >> 5, wk = jkg & 31;
    const float* wbase = W + (size_t)wj * N_ * 512 + wk * 16;
    const int xb = tid & 63, xi = (tid >> 6) * 4;
    const float* xbase = inp + (size_t)xb * N_ * 16 + xi;

    const int jkq = tid & 31;      // jk quads: jkq*4 and 128+jkq*4
    const int bq  = tid >> 5;      // 8-b group (0..7)

    const int total = (N_ - idx + 147) / 148;

    float4 wr0, wr1, wr2, wr3, xr;
    {
        const float* ws = wbase + (size_t)idx * 512;
        wr0 = *reinterpret_cast<const float4*>(ws);
        wr1 = *reinterpret_cast<const float4*>(ws + 4);
        wr2 = *reinterpret_cast<const float4*>(ws + 8);
        wr3 = *reinterpret_cast<const float4*>(ws + 12);
        xr  = *reinterpret_cast<const float4*>(xbase + (size_t)idx * 16);
        Wb[0][0*256+tid]=wr0.x;  Wb[0][1*256+tid]=wr0.y;  Wb[0][2*256+tid]=wr0.z;  Wb[0][3*256+tid]=wr0.w;
        Wb[0][4*256+tid]=wr1.x;  Wb[0][5*256+tid]=wr1.y;  Wb[0][6*256+tid]=wr1.z;  Wb[0][7*256+tid]=wr1.w;
        Wb[0][8*256+tid]=wr2.x;  Wb[0][9*256+tid]=wr2.y;  Wb[0][10*256+tid]=wr2.z; Wb[0][11*256+tid]=wr2.w;
        Wb[0][12*256+tid]=wr3.x; Wb[0][13*256+tid]=wr3.y; Wb[0][14*256+tid]=wr3.z; Wb[0][15*256+tid]=wr3.w;
        Xs[0][(xi + 0) * 64 + xb] = xr.x;
        Xs[0][(xi + 1) * 64 + xb] = xr.y;
        Xs[0][(xi + 2) * 64 + xb] = xr.z;
        Xs[0][(xi + 3) * 64 + xb] = xr.w;
    }

    ull s0a[8][4];
    #pragma unroll
    for (int m = 0; m < 8; m++)
        #pragma unroll
        for (int p = 0; p < 4; p++) s0a[m][p] = 0ull;

    for (int t = 0; t < total; t++) {
        __syncthreads();
        const int ncur = idx + t * 148;
        const bool more = (t + 1 < total);
        if (more) {
            const int nn = ncur + 148;
            const float* ws = wbase + (size_t)nn * 512;
            wr0 = *reinterpret_cast<const float4*>(ws);
            wr1 = *reinterpret_cast<const float4*>(ws + 4);
            wr2 = *reinterpret_cast<const float4*>(ws + 8);
            wr3 = *reinterpret_cast<const float4*>(ws + 12);
            xr  = *reinterpret_cast<const float4*>(xbase + (size_t)nn * 16);
        }
        const float* Wc = Wb[t & 1];
        const float* Xc = Xs[t & 1];

        ull acc[8][4];
        #pragma unroll
        for (int m = 0; m < 8; m++)
            #pragma unroll
            for (int p = 0; p < 4; p++) acc[m][p] = 0ull;

        #pragma unroll
        for (int i = 0; i < 16; i++) {
            float4 wa = *reinterpret_cast<const float4*>(Wc + i * 256 + jkq * 4);
            float4 wb = *reinterpret_cast<const float4*>(Wc + i * 256 + 128 + jkq * 4);
            ull wd0 = dupf(wa.x), wd1 = dupf(wa.y), wd2 = dupf(wa.z), wd3 = dupf(wa.w);
            ull wd4 = dupf(wb.x), wd5 = dupf(wb.y), wd6 = dupf(wb.z), wd7 = dupf(wb.w);
            ulonglong2 xu0 = *reinterpret_cast<const ulonglong2*>(Xc + i * 64 + bq * 8);
            ulonglong2 xu1 = *reinterpret_cast<const ulonglong2*>(Xc + i * 64 + bq * 8 + 4);
            ull xp0 = xu0.x, xp1 = xu0.y, xp2 = xu1.x, xp3 = xu1.y;
            acc[0][0]=fma2(wd0,xp0,acc[0][0]); acc[0][1]=fma2(wd0,xp1,acc[0][1]);
            acc[0][2]=fma2(wd0,xp2,acc[0][2]); acc[0][3]=fma2(wd0,xp3,acc[0][3]);
            acc[1][0]=fma2(wd1,xp0,acc[1][0]); acc[1][1]=fma2(wd1,xp1,acc[1][1]);
            acc[1][2]=fma2(wd1,xp2,acc[1][2]); acc[1][3]=fma2(wd1,xp3,acc[1][3]);
            acc[2][0]=fma2(wd2,xp0,acc[2][0]); acc[2][1]=fma2(wd2,xp1,acc[2][1]);
            acc[2][2]=fma2(wd2,xp2,acc[2][2]); acc[2][3]=fma2(wd2,xp3,acc[2][3]);
            acc[3][0]=fma2(wd3,xp0,acc[3][0]); acc[3][1]=fma2(wd3,xp1,acc[3][1]);
            acc[3][2]=fma2(wd3,xp2,acc[3][2]); acc[3][3]=fma2(wd3,xp3,acc[3][3]);
            acc[4][0]=fma2(wd4,xp0,acc[4][0]); acc[4][1]=fma2(wd4,xp1,acc[4][1]);
            acc[4][2]=fma2(wd4,xp2,acc[4][2]); acc[4][3]=fma2(wd4,xp3,acc[4][3]);
            acc[5][0]=fma2(wd5,xp0,acc[5][0]); acc[5][1]=fma2(wd5,xp1,acc[5][1]);
            acc[5][2]=fma2(wd5,xp2,acc[5][2]); acc[5][3]=fma2(wd5,xp3,acc[5][3]);
            acc[6][0]=fma2(wd6,xp0,acc[6][0]); acc[6][1]=fma2(wd6,xp1,acc[6][1]);
            acc[6][2]=fma2(wd6,xp2,acc[6][2]); acc[6][3]=fma2(wd6,xp3,acc[6][3]);
            acc[7][0]=fma2(wd7,xp0,acc[7][0]); acc[7][1]=fma2(wd7,xp1,acc[7][1]);
            acc[7][2]=fma2(wd7,xp2,acc[7][2]); acc[7][3]=fma2(wd7,xp3,acc[7][3]);
        }

        if (more) {
            float* Wn = Wb[(t + 1) & 1];
            float* Xn = Xs[(t + 1) & 1];
            Wn[0*256+tid]=wr0.x;  Wn[1*256+tid]=wr0.y;  Wn[2*256+tid]=wr0.z;  Wn[3*256+tid]=wr0.w;
            Wn[4*256+tid]=wr1.x;  Wn[5*256+tid]=wr1.y;  Wn[6*256+tid]=wr1.z;  Wn[7*256+tid]=wr1.w;
            Wn[8*256+tid]=wr2.x;  Wn[9*256+tid]=wr2.y;  Wn[10*256+tid]=wr2.z; Wn[11*256+tid]=wr2.w;
            Wn[12*256+tid]=wr3.x; Wn[13*256+tid]=wr3.y; Wn[14*256+tid]=wr3.z; Wn[15*256+tid]=wr3.w;
            Xn[(xi + 0) * 64 + xb] = xr.x;
            Xn[(xi + 1) * 64 + xb] = xr.y;
            Xn[(xi + 2) * 64 + xb] = xr.z;
            Xn[(xi + 3) * 64 + xb] = xr.w;
        }

        // epilogue: s0 += acc; store u_hat fp16
        #pragma unroll
        for (int m = 0; m < 8; m++)
            #pragma unroll
            for (int p = 0; p < 4; p++) s0a[m][p] = add2(s0a[m][p], acc[m][p]);

        #pragma unroll
        for (int p = 0; p < 4; p++) {
            float2 a0 = ull2f2(acc[0][p]), a1 = ull2f2(acc[1][p]);
            float2 a2 = ull2f2(acc[2][p]), a3 = ull2f2(acc[3][p]);
            float2 a4 = ull2f2(acc[4][p]), a5 = ull2f2(acc[5][p]);
            float2 a6 = ull2f2(acc[6][p]), a7 = ull2f2(acc[7][p]);
            #pragma unroll
            for (int e = 0; e < 2; e++) {
                const int bg = bq * 8 + 2 * p + e;
                float f0 = e ? a0.y : a0.x, f1 = e ? a1.y : a1.x;
                float f2 = e ? a2.y : a2.x, f3 = e ? a3.y : a3.x;
                float f4 = e ? a4.y : a4.x, f5 = e ? a5.y : a5.x;
                float f6 = e ? a6.y : a6.x, f7 = e ? a7.y : a7.x;

                __half2 hA0 = __floats2half2_rn(f0, f1), hA1 = __floats2half2_rn(f2, f3);
                __half2 hB0 = __floats2half2_rn(f4, f5), hB1 = __floats2half2_rn(f6, f7);
                __half* up = g_uhat + ((size_t)bg * N_ + ncur) * JK_ + jkQ * 256;
                uint2 vA, vB;
                vA.x = *reinterpret_cast<unsigned int*>(&hA0);
                vA.y = *reinterpret_cast<unsigned int*>(&hA1);
                vB.x = *reinterpret_cast<unsigned int*>(&hB0);
                vB.y = *reinterpret_cast<unsigned int*>(&hB1);
                *reinterpret_cast<uint2*>(up + jkq * 4) = vA;
                *reinterpret_cast<uint2*>(up + 128 + jkq * 4) = vB;
            }
        }
    }

    // flush register s0 (scaled by 1/32)
    #pragma unroll
    for (int p = 0; p < 4; p++) {
        float2 a0 = ull2f2(s0a[0][p]), a1 = ull2f2(s0a[1][p]);
        float2 a2 = ull2f2(s0a[2][p]), a3 = ull2f2(s0a[3][p]);
        float2 a4 = ull2f2(s0a[4][p]), a5 = ull2f2(s0a[5][p]);
        float2 a6 = ull2f2(s0a[6][p]), a7 = ull2f2(s0a[7][p]);
        #pragma unroll
        for (int e = 0; e < 2; e++) {
            const int bg = bq * 8 + 2 * p + e;
            float f0 = (e ? a0.y : a0.x) * 0.03125f, f1 = (e ? a1.y : a1.x) * 0.03125f;
            float f2 = (e ? a2.y : a2.x) * 0.03125f, f3 = (e ? a3.y : a3.x) * 0.03125f;
            float f4 = (e ? a4.y : a4.x) * 0.03125f, f5 = (e ? a5.y : a5.x) * 0.03125f;
            float f6 = (e ? a6.y : a6.x) * 0.03125f, f7 = (e ? a7.y : a7.x) * 0.03125f;
            float* dst = &g_sb[0][bg * JK_ + jkQ * 256];
            red4(dst + jkq * 4,       make_float4(f0, f1, f2, f3));
            red4(dst + 128 + jkq * 4, make_float4(f4, f5, f6, f7));
        }
    }
}

// ---------------- fused squash + routing pass (pair-ILP v3) ----------------
// 2 n-rows per iteration: two independent softmax chains interleaved.
// V slices re-read from smem each pair via volatile LDS (frees 32 regs for
// pair buffers). Math identical to the R5 route.
__global__ void __launch_bounds__(256, 2)
k_route(int ia, int ib, int io, int two) {
    __shared__ float V_sm[1024];
    __shared__ float ws[8 * 1024];     // per-warp s partials

    const float* sa = g_sb[ia];
    const float* sb = g_sb[ib];
    float* sout = g_sb[io];

    const int chunk = blockIdx.x;      // 0..31
    const int b     = blockIdx.y;      // 0..63
    const int tid   = threadIdx.x;     // 256
    const int warp  = tid >> 5;
    const int lane  = tid & 31;

    // --- build V[j][k] = squash(sa) [+ squash(sb)] ---
    #pragma unroll
    for (int r = 0; r < 4; r++) {
        int j = warp * 4 + r;
        float va = sa[b * JK_ + j * 32 + lane];
        float sq = va * va;
        #pragma unroll
        for (int o = 16; o; o >>= 1) sq += __shfl_xor_sync(0xffffffffu, sq, o);
        float val = (sq / ((1.0f + sq) * sqrtf(sq + 1e-7f))) * va;
        if (two) {
            float vb = sb[b * JK_ + j * 32 + lane];
            float sqb = vb * vb;
            #pragma unroll
            for (int o = 16; o; o >>= 1) sqb += __shfl_xor_sync(0xffffffffu, sqb, o);
            val += (sqb / ((1.0f + sqb) * sqrtf(sqb + 1e-7f))) * vb;
        }
        V_sm[j * 32 + lane] = val;
    }
    __syncthreads();

    const uint32_t vbase = smem_addr_u32(V_sm) + lane * 32;   // lane's 8-float slice

    ull sacc[4][4];
    #pragma unroll
    for (int q = 0; q < 4; q++)
        #pragma unroll
        for (int m = 0; m < 4; m++) sacc[q][m] = 0ull;

    const char* row0 = reinterpret_cast<const char*>(
        g_uhat + ((size_t)b * N_ + (size_t)(chunk * 64 + warp * 8)) * JK_) + lane * 16;

    uint4 curA[4], curB[4], nxtA[4], nxtB[4];
    #pragma unroll
    for (int q = 0; q < 4; q++) {
        curA[q] = *reinterpret_cast<const uint4*>(row0 + q * 512);
        curB[q] = *reinterpret_cast<const uint4*>(row0 + 2048 + q * 512);
    }

    #pragma unroll
    for (int p = 0; p < 4; p++) {                 // pair = rows (2p, 2p+1)
        if (p < 3) {
            const char* ra = row0 + (size_t)(2 * p + 2) * 2048;
            #pragma unroll
            for (int q = 0; q < 4; q++) {
                nxtA[q] = *reinterpret_cast<const uint4*>(ra + q * 512);
                nxtB[q] = *reinterpret_cast<const uint4*>(ra + 2048 + q * 512);
            }
        }
        // logits: two independent chains, vq transient per q
        float dA[4], dB[4];
        #pragma unroll
        for (int q = 0; q < 4; q++) {
            ull v0, v1, v2, v3;
            lds_v2u64(v0, v1, vbase + q * 1024);
            lds_v2u64(v2, v3, vbase + q * 1024 + 16);
            ull da = fma2(h2f2(curA[q].x), v0, fma2(h2f2(curA[q].y), v1,
                     fma2(h2f2(curA[q].z), v2, fma2(h2f2(curA[q].w), v3, 0ull))));
            ull db = fma2(h2f2(curB[q].x), v0, fma2(h2f2(curB[q].y), v1,
                     fma2(h2f2(curB[q].z), v2, fma2(h2f2(curB[q].w), v3, 0ull))));
            float2 fa = ull2f2(da);
            float2 fb = ull2f2(db);
            dA[q] = fa.x + fa.y;
            dB[q] = fb.x + fb.y;
        }
        float eA[4], eB[4];
        #pragma unroll
        for (int q = 0; q < 4; q++) {
            float a = dA[q], c = dB[q];
            a += __shfl_xor_sync(0xffffffffu, a, 1);
            c += __shfl_xor_sync(0xffffffffu, c, 1);
            a += __shfl_xor_sync(0xffffffffu, a, 2);
            c += __shfl_xor_sync(0xffffffffu, c, 2);
            eA[q] = __expf(a);           // logits bounded; no max needed
            eB[q] = __expf(c);
        }
        float tA = eA[0] + eA[1] + eA[2] + eA[3];
        float tB = eB[0] + eB[1] + eB[2] + eB[3];
        tA += __shfl_xor_sync(0xffffffffu, tA, 4);
        tB += __shfl_xor_sync(0xffffffffu, tB, 4);
        tA += __shfl_xor_sync(0xffffffffu, tA, 8);
        tB += __shfl_xor_sync(0xffffffffu, tB, 8);
        tA += __shfl_xor_sync(0xffffffffu, tA, 16);
        tB += __shfl_xor_sync(0xffffffffu, tB, 16);
        float invA = __fdividef(1.0f, tA);
        float invB = __fdividef(1.0f, tB);
        #pragma unroll
        for (int q = 0; q < 4; q++) {
            ull cA = dupf(eA[q] * invA);
            ull cB = dupf(eB[q] * invB);
            sacc[q][0] = fma2(cA, h2f2(curA[q].x), fma2(cB, h2f2(curB[q].x), sacc[q][0]));
            sacc[q][1] = fma2(cA, h2f2(curA[q].y), fma2(cB, h2f2(curB[q].y), sacc[q][1]));
            sacc[q][2] = fma2(cA, h2f2(curA[q].z), fma2(cB, h2f2(curB[q].z), sacc[q][2]));
            sacc[q][3] = fma2(cA, h2f2(curA[q].w), fma2(cB, h2f2(curB[q].w), sacc[q][3]));
        }
        if (p < 3) {
            #pragma unroll
            for (int q = 0; q < 4; q++) { curA[q] = nxtA[q]; curB[q] = nxtB[q]; }
        }
    }

    // per-warp private store (no atomics)
    #pragma unroll
    for (int q = 0; q < 4; q++) {
        float2 f0 = ull2f2(sacc[q][0]), f1 = ull2f2(sacc[q][1]);
        float2 f2 = ull2f2(sacc[q][2]), f3 = ull2f2(sacc[q][3]);
        float* wp = ws + warp * 1024 + q * 256 + lane * 8;
        *reinterpret_cast<float4*>(wp)     = make_float4(f0.x, f0.y, f1.x, f1.y);
        *reinterpret_cast<float4*>(wp + 4) = make_float4(f2.x, f2.y, f3.x, f3.y);
    }
    __syncthreads();

    // cross-warp tree reduce + global flush
    float4 a = *reinterpret_cast<const float4*>(ws + tid * 4);
    #pragma unroll
    for (int w = 1; w < 8; w++) {
        float4 x = *reinterpret_cast<const float4*>(ws + w * 1024 + tid * 4);
        a.x += x.x; a.y += x.y; a.z += x.z; a.w += x.w;
    }
    red4(sout + b * JK_ + tid * 4, a);
}

// ---------------- final squash ----------------
__global__ void __launch_bounds__(1024) k_squash_final(float* __restrict__ out) {
    const int b   = blockIdx.x;
    const int tid = threadIdx.x;      // warp = j, lane = k
    float sv = g_sb[2][b * JK_ + tid];
    float sq = sv * sv;
    #pragma unroll
    for (int o = 16; o; o >>= 1) sq += __shfl_xor_sync(0xffffffffu, sq, o);
    out[b * JK_ + tid] = (sq / ((1.0f + sq) * sqrtf(sq + 1e-7f))) * sv;
}

extern "C" void kernel_launch(void* const* d_in, const int* in_sizes, int n_in,
                              void* d_out, int out_size) {
    const float* inp = (const float*)d_in[0];   // [64, 2048, 16]
    const float* W   = (const float*)d_in[1];   // [32, 2048, 32, 16]
    float* out = (float*)d_out;                 // [64, 32, 32]

    k_init<<<192, 1024>>>();                    // zero s0,s1,s2
    k_uhat<<<592, 256>>>(inp, W);               // u_hat + s0
    k_route<<<dim3(32, 64), 256>>>(0, 0, 1, 0); // V0 -> s1   (ncu #4)
    k_route<<<dim3(32, 64), 256>>>(0, 1, 2, 1); // V0+V1 -> s2
    k_squash_final<<<64, 1024>>>(out);
}

// round 12
// speedup vs baseline: 1.4707x; 1.0712x over previous
#include <cuda_runtime.h>
#include <cuda_fp16.h>
#include <cstdint>

#define B_  64
#define N_  2048
#define I_  16
#define JK_ 1024

typedef unsigned long long ull;

// Scratch: u_hat fp16 [b][n][jk] (256 MB); three s buffers (iter 0,1,2)
__device__ __half g_uhat[(size_t)B_ * N_ * JK_];
__device__ float  g_sb[3][B_ * JK_];

// ---------------- packed fp32x2 helpers (sm_100+) ----------------
static __device__ __forceinline__ ull fma2(ull a, ull b, ull c) {
    ull d;
    asm("fma.rn.f32x2 %0, %1, %2, %3;" : "=l"(d) : "l"(a), "l"(b), "l"(c));
    return d;
}
static __device__ __forceinline__ ull add2(ull a, ull b) {
    ull d;
    asm("add.rn.f32x2 %0, %1, %2;" : "=l"(d) : "l"(a), "l"(b));
    return d;
}
static __device__ __forceinline__ float2 ull2f2(ull v) {
    float2 f;
    asm("mov.b64 {%0, %1}, %2;" : "=f"(f.x), "=f"(f.y) : "l"(v));
    return f;
}
static __device__ __forceinline__ ull packf2(float x, float y) {
    ull r;
    asm("mov.b64 %0, {%1, %2};" : "=l"(r) : "f"(x), "f"(y));
    return r;
}
static __device__ __forceinline__ ull dupf(float x) {
    ull r;
    asm("mov.b64 %0, {%1, %1};" : "=l"(r) : "f"(x));
    return r;
}
static __device__ __forceinline__ ull h2f2(unsigned int h) {
    __half2 hh = *reinterpret_cast<__half2*>(&h);
    float2 f = __half22float2(hh);
    return packf2(f.x, f.y);
}
static __device__ __forceinline__ void red4(float* p, float4 v) {
    asm volatile("red.global.add.v4.f32 [%0], {%1,%2,%3,%4};"
                 :: "l"(p), "f"(v.x), "f"(v.y), "f"(v.z), "f"(v.w) : "memory");
}
static __device__ __forceinline__ uint32_t smem_addr_u32(const void* p) {
    uint32_t a;
    asm("{ .reg .u64 t; cvta.to.shared.u64 t, %1; cvt.u32.u64 %0, t; }"
        : "=r"(a) : "l"(p));
    return a;
}
static __device__ __forceinline__ void cp_async16(uint32_t saddr, const void* gaddr) {
    asm volatile("cp.async.cg.shared.global [%0], [%1], 16;"
                 :: "r"(saddr), "l"(gaddr) : "memory");
}
static __device__ __forceinline__ void cp_commit() {
    asm volatile("cp.async.commit_group;" ::: "memory");
}
template <int N>
static __device__ __forceinline__ void cp_wait() {
    asm volatile("cp.async.wait_group %0;" :: "n"(N) : "memory");
}

__global__ void __launch_bounds__(1024) k_init() {
    int idx = blockIdx.x * 1024 + threadIdx.x;   // grid 192 -> 196608
    (&g_sb[0][0])[idx] = 0.0f;
}

// ---------------- fused u_hat generation + iteration-0 s ----------------
// (R10 version, 2 CTAs/SM; est ~126us)
__global__ void __launch_bounds__(256, 2) k_uhat(const float* __restrict__ inp,
                                                 const float* __restrict__ W) {
    __shared__ float Wb[2][16 * 256];   // [buf][i][jk_local]  2x16KB
    __shared__ float Xs[2][16 * 64];    // [buf][i][b]         2x4KB

    const int tid = threadIdx.x;
    const int jkQ = blockIdx.x & 3;     // jk quarter
    const int idx = blockIdx.x >> 2;    // n-strip 0..147

    const int jkg = jkQ * 256 + tid;
    const int wj = jkg >> 5, wk = jkg & 31;
    const float* wbase = W + (size_t)wj * N_ * 512 + wk * 16;
    const int xb = tid & 63, xi = (tid >> 6) * 4;
    const float* xbase = inp + (size_t)xb * N_ * 16 + xi;

    const int jkq = tid & 31;      // jk quads: jkq*4 and 128+jkq*4
    const int bq  = tid >> 5;      // 8-b group (0..7)

    const int total = (N_ - idx + 147) / 148;

    float4 wr0, wr1, wr2, wr3, xr;
    {
        const float* ws = wbase + (size_t)idx * 512;
        wr0 = *reinterpret_cast<const float4*>(ws);
        wr1 = *reinterpret_cast<const float4*>(ws + 4);
        wr2 = *reinterpret_cast<const float4*>(ws + 8);
        wr3 = *reinterpret_cast<const float4*>(ws + 12);
        xr  = *reinterpret_cast<const float4*>(xbase + (size_t)idx * 16);
        Wb[0][0*256+tid]=wr0.x;  Wb[0][1*256+tid]=wr0.y;  Wb[0][2*256+tid]=wr0.z;  Wb[0][3*256+tid]=wr0.w;
        Wb[0][4*256+tid]=wr1.x;  Wb[0][5*256+tid]=wr1.y;  Wb[0][6*256+tid]=wr1.z;  Wb[0][7*256+tid]=wr1.w;
        Wb[0][8*256+tid]=wr2.x;  Wb[0][9*256+tid]=wr2.y;  Wb[0][10*256+tid]=wr2.z; Wb[0][11*256+tid]=wr2.w;
        Wb[0][12*256+tid]=wr3.x; Wb[0][13*256+tid]=wr3.y; Wb[0][14*256+tid]=wr3.z; Wb[0][15*256+tid]=wr3.w;
        Xs[0][(xi + 0) * 64 + xb] = xr.x;
        Xs[0][(xi + 1) * 64 + xb] = xr.y;
        Xs[0][(xi + 2) * 64 + xb] = xr.z;
        Xs[0][(xi + 3) * 64 + xb] = xr.w;
    }

    ull s0a[8][4];
    #pragma unroll
    for (int m = 0; m < 8; m++)
        #pragma unroll
        for (int p = 0; p < 4; p++) s0a[m][p] = 0ull;

    for (int t = 0; t < total; t++) {
        __syncthreads();
        const int ncur = idx + t * 148;
        const bool more = (t + 1 < total);
        if (more) {
            const int nn = ncur + 148;
            const float* ws = wbase + (size_t)nn * 512;
            wr0 = *reinterpret_cast<const float4*>(ws);
            wr1 = *reinterpret_cast<const float4*>(ws + 4);
            wr2 = *reinterpret_cast<const float4*>(ws + 8);
            wr3 = *reinterpret_cast<const float4*>(ws + 12);
            xr  = *reinterpret_cast<const float4*>(xbase + (size_t)nn * 16);
        }
        const float* Wc = Wb[t & 1];
        const float* Xc = Xs[t & 1];

        ull acc[8][4];
        #pragma unroll
        for (int m = 0; m < 8; m++)
            #pragma unroll
            for (int p = 0; p < 4; p++) acc[m][p] = 0ull;

        #pragma unroll
        for (int i = 0; i < 16; i++) {
            float4 wa = *reinterpret_cast<const float4*>(Wc + i * 256 + jkq * 4);
            float4 wb = *reinterpret_cast<const float4*>(Wc + i * 256 + 128 + jkq * 4);
            ull wd0 = dupf(wa.x), wd1 = dupf(wa.y), wd2 = dupf(wa.z), wd3 = dupf(wa.w);
            ull wd4 = dupf(wb.x), wd5 = dupf(wb.y), wd6 = dupf(wb.z), wd7 = dupf(wb.w);
            ulonglong2 xu0 = *reinterpret_cast<const ulonglong2*>(Xc + i * 64 + bq * 8);
            ulonglong2 xu1 = *reinterpret_cast<const ulonglong2*>(Xc + i * 64 + bq * 8 + 4);
            ull xp0 = xu0.x, xp1 = xu0.y, xp2 = xu1.x, xp3 = xu1.y;
            acc[0][0]=fma2(wd0,xp0,acc[0][0]); acc[0][1]=fma2(wd0,xp1,acc[0][1]);
            acc[0][2]=fma2(wd0,xp2,acc[0][2]); acc[0][3]=fma2(wd0,xp3,acc[0][3]);
            acc[1][0]=fma2(wd1,xp0,acc[1][0]); acc[1][1]=fma2(wd1,xp1,acc[1][1]);
            acc[1][2]=fma2(wd1,xp2,acc[1][2]); acc[1][3]=fma2(wd1,xp3,acc[1][3]);
            acc[2][0]=fma2(wd2,xp0,acc[2][0]); acc[2][1]=fma2(wd2,xp1,acc[2][1]);
            acc[2][2]=fma2(wd2,xp2,acc[2][2]); acc[2][3]=fma2(wd2,xp3,acc[2][3]);
            acc[3][0]=fma2(wd3,xp0,acc[3][0]); acc[3][1]=fma2(wd3,xp1,acc[3][1]);
            acc[3][2]=fma2(wd3,xp2,acc[3][2]); acc[3][3]=fma2(wd3,xp3,acc[3][3]);
            acc[4][0]=fma2(wd4,xp0,acc[4][0]); acc[4][1]=fma2(wd4,xp1,acc[4][1]);
            acc[4][2]=fma2(wd4,xp2,acc[4][2]); acc[4][3]=fma2(wd4,xp3,acc[4][3]);
            acc[5][0]=fma2(wd5,xp0,acc[5][0]); acc[5][1]=fma2(wd5,xp1,acc[5][1]);
            acc[5][2]=fma2(wd5,xp2,acc[5][2]); acc[5][3]=fma2(wd5,xp3,acc[5][3]);
            acc[6][0]=fma2(wd6,xp0,acc[6][0]); acc[6][1]=fma2(wd6,xp1,acc[6][1]);
            acc[6][2]=fma2(wd6,xp2,acc[6][2]); acc[6][3]=fma2(wd6,xp3,acc[6][3]);
            acc[7][0]=fma2(wd7,xp0,acc[7][0]); acc[7][1]=fma2(wd7,xp1,acc[7][1]);
            acc[7][2]=fma2(wd7,xp2,acc[7][2]); acc[7][3]=fma2(wd7,xp3,acc[7][3]);
        }

        if (more) {
            float* Wn = Wb[(t + 1) & 1];
            float* Xn = Xs[(t + 1) & 1];
            Wn[0*256+tid]=wr0.x;  Wn[1*256+tid]=wr0.y;  Wn[2*256+tid]=wr0.z;  Wn[3*256+tid]=wr0.w;
            Wn[4*256+tid]=wr1.x;  Wn[5*256+tid]=wr1.y;  Wn[6*256+tid]=wr1.z;  Wn[7*256+tid]=wr1.w;
            Wn[8*256+tid]=wr2.x;  Wn[9*256+tid]=wr2.y;  Wn[10*256+tid]=wr2.z; Wn[11*256+tid]=wr2.w;
            Wn[12*256+tid]=wr3.x; Wn[13*256+tid]=wr3.y; Wn[14*256+tid]=wr3.z; Wn[15*256+tid]=wr3.w;
            Xn[(xi + 0) * 64 + xb] = xr.x;
            Xn[(xi + 1) * 64 + xb] = xr.y;
            Xn[(xi + 2) * 64 + xb] = xr.z;
            Xn[(xi + 3) * 64 + xb] = xr.w;
        }

        // epilogue: s0 += acc; store u_hat fp16
        #pragma unroll
        for (int m = 0; m < 8; m++)
            #pragma unroll
            for (int p = 0; p < 4; p++) s0a[m][p] = add2(s0a[m][p], acc[m][p]);

        #pragma unroll
        for (int p = 0; p < 4; p++) {
            float2 a0 = ull2f2(acc[0][p]), a1 = ull2f2(acc[1][p]);
            float2 a2 = ull2f2(acc[2][p]), a3 = ull2f2(acc[3][p]);
            float2 a4 = ull2f2(acc[4][p]), a5 = ull2f2(acc[5][p]);
            float2 a6 = ull2f2(acc[6][p]), a7 = ull2f2(acc[7][p]);
            #pragma unroll
            for (int e = 0; e < 2; e++) {
                const int bg = bq * 8 + 2 * p + e;
                float f0 = e ? a0.y : a0.x, f1 = e ? a1.y : a1.x;
                float f2 = e ? a2.y : a2.x, f3 = e ? a3.y : a3.x;
                float f4 = e ? a4.y : a4.x, f5 = e ? a5.y : a5.x;
                float f6 = e ? a6.y : a6.x, f7 = e ? a7.y : a7.x;

                __half2 hA0 = __floats2half2_rn(f0, f1), hA1 = __floats2half2_rn(f2, f3);
                __half2 hB0 = __floats2half2_rn(f4, f5), hB1 = __floats2half2_rn(f6, f7);
                __half* up = g_uhat + ((size_t)bg * N_ + ncur) * JK_ + jkQ * 256;
                uint2 vA, vB;
                vA.x = *reinterpret_cast<unsigned int*>(&hA0);
                vA.y = *reinterpret_cast<unsigned int*>(&hA1);
                vB.x = *reinterpret_cast<unsigned int*>(&hB0);
                vB.y = *reinterpret_cast<unsigned int*>(&hB1);
                *reinterpret_cast<uint2*>(up + jkq * 4) = vA;
                *reinterpret_cast<uint2*>(up + 128 + jkq * 4) = vB;
            }
        }
    }

    // flush register s0 (scaled by 1/32)
    #pragma unroll
    for (int p = 0; p < 4; p++) {
        float2 a0 = ull2f2(s0a[0][p]), a1 = ull2f2(s0a[1][p]);
        float2 a2 = ull2f2(s0a[2][p]), a3 = ull2f2(s0a[3][p]);
        float2 a4 = ull2f2(s0a[4][p]), a5 = ull2f2(s0a[5][p]);
        float2 a6 = ull2f2(s0a[6][p]), a7 = ull2f2(s0a[7][p]);
        #pragma unroll
        for (int e = 0; e < 2; e++) {
            const int bg = bq * 8 + 2 * p + e;
            float f0 = (e ? a0.y : a0.x) * 0.03125f, f1 = (e ? a1.y : a1.x) * 0.03125f;
            float f2 = (e ? a2.y : a2.x) * 0.03125f, f3 = (e ? a3.y : a3.x) * 0.03125f;
            float f4 = (e ? a4.y : a4.x) * 0.03125f, f5 = (e ? a5.y : a5.x) * 0.03125f;
            float f6 = (e ? a6.y : a6.x) * 0.03125f, f7 = (e ? a7.y : a7.x) * 0.03125f;
            float* dst = &g_sb[0][bg * JK_ + jkQ * 256];
            red4(dst + jkq * 4,       make_float4(f0, f1, f2, f3));
            red4(dst + 128 + jkq * 4, make_float4(f4, f5, f6, f7));
        }
    }
}

// ---------------- fused squash + routing pass (cp.async ring v4) ----------
// Each warp streams its 8 rows through a 4-slot smem ring via cp.async
// (16B/lane, lane-private slots: no syncs, no swizzle). 4-row pipeline
// depth covers DRAM latency. Compute body identical to the R5 route.
__global__ void __launch_bounds__(256, 2)
k_route(int ia, int ib, int io, int two) {
    extern __shared__ float smr[];
    float* V_sm = smr;            // 1024 floats (4 KB)
    float* ws   = smr + 1024;     // 8192 floats (32 KB)
    float* ring = smr + 9216;     // 16384 floats (64 KB): warp*2048 + slot*512

    const float* sa = g_sb[ia];
    const float* sb = g_sb[ib];
    float* sout = g_sb[io];

    const int chunk = blockIdx.x;      // 0..31
    const int b     = blockIdx.y;      // 0..63
    const int tid   = threadIdx.x;     // 256
    const int warp  = tid >> 5;
    const int lane  = tid & 31;

    // --- build V[j][k] = squash(sa) [+ squash(sb)] ---
    #pragma unroll
    for (int r = 0; r < 4; r++) {
        int j = warp * 4 + r;
        float va = sa[b * JK_ + j * 32 + lane];
        float sq = va * va;
        #pragma unroll
        for (int o = 16; o; o >>= 1) sq += __shfl_xor_sync(0xffffffffu, sq, o);
        float val = (sq / ((1.0f + sq) * sqrtf(sq + 1e-7f))) * va;
        if (two) {
            float vb = sb[b * JK_ + j * 32 + lane];
            float sqb = vb * vb;
            #pragma unroll
            for (int o = 16; o; o >>= 1) sqb += __shfl_xor_sync(0xffffffffu, sqb, o);
            val += (sqb / ((1.0f + sqb) * sqrtf(sqb + 1e-7f))) * vb;
        }
        V_sm[j * 32 + lane] = val;
    }
    __syncthreads();

    // lane's V slice: for q, jk = q*256 + lane*8 .. +7
    ull vq[4][4];
    #pragma unroll
    for (int q = 0; q < 4; q++) {
        float4 a = *reinterpret_cast<const float4*>(V_sm + q * 256 + lane * 8);
        float4 c = *reinterpret_cast<const float4*>(V_sm + q * 256 + lane * 8 + 4);
        vq[q][0] = packf2(a.x, a.y); vq[q][1] = packf2(a.z, a.w);
        vq[q][2] = packf2(c.x, c.y); vq[q][3] = packf2(c.z, c.w);
    }

    ull sacc[4][4];
    #pragma unroll
    for (int q = 0; q < 4; q++)
        #pragma unroll
        for (int m = 0; m < 4; m++) sacc[q][m] = 0ull;

    // global row base (bytes); row stride 2048B; lane offset within q-chunk
    const char* row0 = reinterpret_cast<const char*>(
        g_uhat + ((size_t)b * N_ + (size_t)(chunk * 64 + warp * 8)) * JK_) + lane * 16;
    // smem ring base for this warp/lane (bytes); slot stride 2048B
    const uint32_t rbase = smem_addr_u32(ring) + warp * 8192 + lane * 16;

    // prologue: rows 0..3 into slots 0..3
    #pragma unroll
    for (int r = 0; r < 4; r++) {
        #pragma unroll
        for (int q = 0; q < 4; q++)
            cp_async16(rbase + r * 2048 + q * 512, row0 + (size_t)r * 2048 + q * 512);
        cp_commit();
    }

    #pragma unroll
    for (int r = 0; r < 8; r++) {
        // wait until row r's group is complete
        if (r <= 4)      cp_wait<3>();
        else if (r == 5) cp_wait<2>();
        else if (r == 6) cp_wait<1>();
        else             cp_wait<0>();

        const float* slot = ring + (size_t)(warp * 2048 + (r & 3) * 512) + lane * 4;
        uint4 c4[4];
        #pragma unroll
        for (int q = 0; q < 4; q++)
            c4[q] = *reinterpret_cast<const uint4*>(slot + q * 128);

        // refill slot with row r+4
        if (r < 4) {
            #pragma unroll
            for (int q = 0; q < 4; q++)
                cp_async16(rbase + (r & 3) * 2048 + q * 512,
                           row0 + (size_t)(r + 4) * 2048 + q * 512);
            cp_commit();
        }

        float e[4];
        #pragma unroll
        for (int q = 0; q < 4; q++) {
            ull u0 = h2f2(c4[q].x), u1 = h2f2(c4[q].y);
            ull u2 = h2f2(c4[q].z), u3 = h2f2(c4[q].w);
            ull d = fma2(u0, vq[q][0], fma2(u1, vq[q][1],
                    fma2(u2, vq[q][2], fma2(u3, vq[q][3], 0ull))));
            float2 df = ull2f2(d);
            float bp = df.x + df.y;
            bp += __shfl_xor_sync(0xffffffffu, bp, 1);
            bp += __shfl_xor_sync(0xffffffffu, bp, 2);
            e[q] = __expf(bp);          // logits bounded; no max needed
        }
        float tot = e[0] + e[1] + e[2] + e[3];
        tot += __shfl_xor_sync(0xffffffffu, tot, 4);
        tot += __shfl_xor_sync(0xffffffffu, tot, 8);
        tot += __shfl_xor_sync(0xffffffffu, tot, 16);
        float inv = __fdividef(1.0f, tot);
        #pragma unroll
        for (int q = 0; q < 4; q++) {
            ull cq2 = dupf(e[q] * inv);
            ull u0 = h2f2(c4[q].x), u1 = h2f2(c4[q].y);
            ull u2 = h2f2(c4[q].z), u3 = h2f2(c4[q].w);
            sacc[q][0] = fma2(cq2, u0, sacc[q][0]);
            sacc[q][1] = fma2(cq2, u1, sacc[q][1]);
            sacc[q][2] = fma2(cq2, u2, sacc[q][2]);
            sacc[q][3] = fma2(cq2, u3, sacc[q][3]);
        }
    }

    // per-warp private store (no atomics)
    #pragma unroll
    for (int q = 0; q < 4; q++) {
        float2 f0 = ull2f2(sacc[q][0]), f1 = ull2f2(sacc[q][1]);
        float2 f2 = ull2f2(sacc[q][2]), f3 = ull2f2(sacc[q][3]);
        float* wp = ws + warp * 1024 + q * 256 + lane * 8;
        *reinterpret_cast<float4*>(wp)     = make_float4(f0.x, f0.y, f1.x, f1.y);
        *reinterpret_cast<float4*>(wp + 4) = make_float4(f2.x, f2.y, f3.x, f3.y);
    }
    __syncthreads();

    // cross-warp tree reduce + global flush
    float4 a = *reinterpret_cast<const float4*>(ws + tid * 4);
    #pragma unroll
    for (int w = 1; w < 8; w++) {
        float4 x = *reinterpret_cast<const float4*>(ws + w * 1024 + tid * 4);
        a.x += x.x; a.y += x.y; a.z += x.z; a.w += x.w;
    }
    red4(sout + b * JK_ + tid * 4, a);
}

// ---------------- final squash ----------------
__global__ void __launch_bounds__(1024) k_squash_final(float* __restrict__ out) {
    const int b   = blockIdx.x;
    const int tid = threadIdx.x;      // warp = j, lane = k
    float sv = g_sb[2][b * JK_ + tid];
    float sq = sv * sv;
    #pragma unroll
    for (int o = 16; o; o >>= 1) sq += __shfl_xor_sync(0xffffffffu, sq, o);
    out[b * JK_ + tid] = (sq / ((1.0f + sq) * sqrtf(sq + 1e-7f))) * sv;
}

extern "C" void kernel_launch(void* const* d_in, const int* in_sizes, int n_in,
                              void* d_out, int out_size) {
    const float* inp = (const float*)d_in[0];   // [64, 2048, 16]
    const float* W   = (const float*)d_in[1];   // [32, 2048, 32, 16]
    float* out = (float*)d_out;                 // [64, 32, 32]

    cudaFuncSetAttribute(k_route, cudaFuncAttributeMaxDynamicSharedMemorySize, 102400);

    k_init<<<192, 1024>>>();                            // zero s0,s1,s2
    k_uhat<<<592, 256>>>(inp, W);                       // u_hat + s0
    k_route<<<dim3(32, 64), 256, 102400>>>(0, 0, 1, 0); // V0 -> s1
    k_route<<<dim3(32, 64), 256, 102400>>>(0, 1, 2, 1); // V0+V1 -> s2
    k_squash_final<<<64, 1024>>>(out);
}

// round 14
// speedup vs baseline: 1.5107x; 1.0272x over previous
#include <cuda_runtime.h>
#include <cuda_fp16.h>
#include <cstdint>

#define B_  64
#define N_  2048
#define I_  16
#define JK_ 1024

typedef unsigned long long ull;

// Scratch: u_hat fp16 [b][n][jk] (256 MB); three s buffers (iter 0,1,2)
__device__ __half g_uhat[(size_t)B_ * N_ * JK_];
__device__ float  g_sb[3][B_ * JK_];

// ---------------- packed fp32x2 helpers (sm_100+) ----------------
static __device__ __forceinline__ ull fma2(ull a, ull b, ull c) {
    ull d;
    asm("fma.rn.f32x2 %0, %1, %2, %3;" : "=l"(d) : "l"(a), "l"(b), "l"(c));
    return d;
}
static __device__ __forceinline__ float2 ull2f2(ull v) {
    float2 f;
    asm("mov.b64 {%0, %1}, %2;" : "=f"(f.x), "=f"(f.y) : "l"(v));
    return f;
}
static __device__ __forceinline__ ull packf2(float x, float y) {
    ull r;
    asm("mov.b64 %0, {%1, %2};" : "=l"(r) : "f"(x), "f"(y));
    return r;
}
static __device__ __forceinline__ ull dupf(float x) {
    ull r;
    asm("mov.b64 %0, {%1, %1};" : "=l"(r) : "f"(x));
    return r;
}
static __device__ __forceinline__ ull h2f2(unsigned int h) {
    __half2 hh = *reinterpret_cast<__half2*>(&h);
    float2 f = __half22float2(hh);
    return packf2(f.x, f.y);
}
static __device__ __forceinline__ void red4(float* p, float4 v) {
    asm volatile("red.global.add.v4.f32 [%0], {%1,%2,%3,%4};"
                 :: "l"(p), "f"(v.x), "f"(v.y), "f"(v.z), "f"(v.w) : "memory");
}
static __device__ __forceinline__ void redf(float* p, float v) {
    asm volatile("red.global.add.f32 [%0], %1;" :: "l"(p), "f"(v) : "memory");
}
static __device__ __forceinline__ uint32_t smem_u32(const void* p) {
    uint32_t a;
    asm("{ .reg .u64 t; cvta.to.shared.u64 t, %1; cvt.u32.u64 %0, t; }"
        : "=r"(a) : "l"(p));
    return a;
}
static __device__ __forceinline__ void cp_async16(uint32_t saddr, const void* gaddr) {
    asm volatile("cp.async.cg.shared.global [%0], [%1], 16;"
                 :: "r"(saddr), "l"(gaddr) : "memory");
}
static __device__ __forceinline__ void cp_commit() {
    asm volatile("cp.async.commit_group;" ::: "memory");
}
template <int N>
static __device__ __forceinline__ void cp_wait() {
    asm volatile("cp.async.wait_group %0;" :: "n"(N) : "memory");
}
// Ampere-class HMMA: m16n8k16, f16 in / f32 accum (baseline PTX, compute_103-safe)
static __device__ __forceinline__ void mma16816(float* d,
                                                uint32_t a0, uint32_t a1,
                                                uint32_t a2, uint32_t a3,
                                                uint32_t b0, uint32_t b1) {
    asm("mma.sync.aligned.m16n8k16.row.col.f32.f16.f16.f32 "
        "{%0,%1,%2,%3}, {%4,%5,%6,%7}, {%8,%9}, {%10,%11,%12,%13};"
        : "=f"(d[0]), "=f"(d[1]), "=f"(d[2]), "=f"(d[3])
        : "r"(a0), "r"(a1), "r"(a2), "r"(a3), "r"(b0), "r"(b1),
          "f"(0.0f), "f"(0.0f), "f"(0.0f), "f"(0.0f));
}
static __device__ __forceinline__ unsigned int f2h2(float x, float y) {
    __half2 h = __floats2half2_rn(x, y);
    return *reinterpret_cast<unsigned int*>(&h);
}

__global__ void __launch_bounds__(1024) k_init() {
    int idx = blockIdx.x * 1024 + threadIdx.x;   // grid 192 -> 196608
    (&g_sb[0][0])[idx] = 0.0f;
}

// ---------------- HMMA u_hat generation + s0 ----------------
// Grid 1184 = 148 n-strips x 8 jk-eighths, 256 thr, 2 CTAs/SM.
// Per n: D[b 64, jk 128] = X[b,i] * W[jk,i]^T via 64 HMMA m16n8k16
// (A = X row-major, B = W col-major(N x K), K = 16 = one MMA).
// s0 accumulated in fragment-layout registers; u_hat bounced through a
// padded smem tile for coalesced 16B stores.
#define TS 24     // staged tile row stride (halfs); bank-conflict-free frags
#define DS 136    // D bounce tile row stride (halfs)
__global__ void __launch_bounds__(256, 2) k_uhat(const float* __restrict__ inp,
                                                 const float* __restrict__ W) {
    __shared__ __half Wt[2][128 * TS];   // [buf][jk][i]  2x6KB
    __shared__ __half Xt[2][64 * TS];    // [buf][b][i]   2x3KB
    __shared__ __half Dsm[64 * DS];      // D bounce      17KB

    const int tid = threadIdx.x;
    const int w = tid >> 5, l = tid & 31;
    const int g = l >> 2, t = l & 3;     // fragment group / thread-in-group
    const int jkQ = blockIdx.x & 7;      // jk eighth (128 jk)
    const int idx = blockIdx.x >> 3;     // n-strip 0..147

    // staging sources
    const int wr_ = tid >> 1;            // W row to stage (0..127)
    const int wi  = (tid & 1) * 8;       // i half
    const int jkg = jkQ * 128 + wr_;
    const float* wsrc = W + ((size_t)(jkg >> 5) * N_) * 512
                        + (size_t)(jkg & 31) * 16 + wi;
    const int xb = tid >> 2, xi4 = (tid & 3) * 4;
    const float* xsrc = inp + (size_t)xb * N_ * 16 + xi4;

    const int total = (N_ - idx + 147) / 148;

    float4 wv0, wv1, xv;
    {   // prologue: stage n0 into buffer 0
        const float* ws = wsrc + (size_t)idx * 512;
        wv0 = *reinterpret_cast<const float4*>(ws);
        wv1 = *reinterpret_cast<const float4*>(ws + 4);
        xv  = *reinterpret_cast<const float4*>(xsrc + (size_t)idx * 16);
        uint4 v;
        v.x = f2h2(wv0.x, wv0.y); v.y = f2h2(wv0.z, wv0.w);
        v.z = f2h2(wv1.x, wv1.y); v.w = f2h2(wv1.z, wv1.w);
        *reinterpret_cast<uint4*>(Wt[0] + wr_ * TS + wi) = v;
        uint2 xu;
        xu.x = f2h2(xv.x, xv.y); xu.y = f2h2(xv.z, xv.w);
        *reinterpret_cast<uint2*>(Xt[0] + xb * TS + xi4) = xu;
    }

    float s0r[8][4];
    #pragma unroll
    for (int j = 0; j < 8; j++)
        #pragma unroll
        for (int k = 0; k < 4; k++) s0r[j][k] = 0.0f;

    const int btile = w & 3;             // warp's b tile (16 b)
    const int jhalf = w >> 2;            // warp's jk half (64 jk)
    const int arow  = btile * 16 + g;

    for (int it = 0; it < total; it++) {
        __syncthreads();
        const int n = idx + it * 148;
        const bool more = (it + 1 < total);
        if (more) {
            const int nn = n + 148;
            const float* ws = wsrc + (size_t)nn * 512;
            wv0 = *reinterpret_cast<const float4*>(ws);
            wv1 = *reinterpret_cast<const float4*>(ws + 4);
            xv  = *reinterpret_cast<const float4*>(xsrc + (size_t)nn * 16);
        }
        const __half* Wc = Wt[it & 1];
        const __half* Xc = Xt[it & 1];

        // A fragments (X): rows arow, arow+8; k pairs 2t, 2t+8
        uint32_t ra0 = *reinterpret_cast<const uint32_t*>(Xc + arow * TS + 2 * t);
        uint32_t ra1 = *reinterpret_cast<const uint32_t*>(Xc + (arow + 8) * TS + 2 * t);
        uint32_t ra2 = *reinterpret_cast<const uint32_t*>(Xc + arow * TS + 2 * t + 8);
        uint32_t ra3 = *reinterpret_cast<const uint32_t*>(Xc + (arow + 8) * TS + 2 * t + 8);

        float acc[8][4];
        #pragma unroll
        for (int j8 = 0; j8 < 8; j8++) {
            const int brow = jhalf * 64 + j8 * 8 + g;
            uint32_t rb0 = *reinterpret_cast<const uint32_t*>(Wc + brow * TS + 2 * t);
            uint32_t rb1 = *reinterpret_cast<const uint32_t*>(Wc + brow * TS + 2 * t + 8);
            mma16816(acc[j8], ra0, ra1, ra2, ra3, rb0, rb1);
        }

        if (more) {   // stage next n into other buffer
            const int nb = (it + 1) & 1;
            uint4 v;
            v.x = f2h2(wv0.x, wv0.y); v.y = f2h2(wv0.z, wv0.w);
            v.z = f2h2(wv1.x, wv1.y); v.w = f2h2(wv1.z, wv1.w);
            *reinterpret_cast<uint4*>(Wt[nb] + wr_ * TS + wi) = v;
            uint2 xu;
            xu.x = f2h2(xv.x, xv.y); xu.y = f2h2(xv.z, xv.w);
            *reinterpret_cast<uint2*>(Xt[nb] + xb * TS + xi4) = xu;
        }

        // s0 += acc; D -> bounce tile (half2 per pair, conflict-free)
        #pragma unroll
        for (int j8 = 0; j8 < 8; j8++) {
            s0r[j8][0] += acc[j8][0]; s0r[j8][1] += acc[j8][1];
            s0r[j8][2] += acc[j8][2]; s0r[j8][3] += acc[j8][3];
            const int jkl = jhalf * 64 + j8 * 8 + 2 * t;
            *reinterpret_cast<__half2*>(Dsm + arow * DS + jkl) =
                __floats2half2_rn(acc[j8][0], acc[j8][1]);
            *reinterpret_cast<__half2*>(Dsm + (arow + 8) * DS + jkl) =
                __floats2half2_rn(acc[j8][2], acc[j8][3]);
        }
        __syncthreads();

        // coalesced u_hat store: thread = (b = tid>>2, 64B chunk = tid&3)
        {
            const __half* sp = Dsm + (tid >> 2) * DS + (tid & 3) * 32;
            __half* up = g_uhat + ((size_t)(tid >> 2) * N_ + n) * JK_
                         + jkQ * 128 + (tid & 3) * 32;
            #pragma unroll
            for (int k = 0; k < 4; k++)
                reinterpret_cast<uint4*>(up)[k] =
                    reinterpret_cast<const uint4*>(sp)[k];
        }
    }

    // flush s0 (x 1/32): fragment-layout scalar reductions (one-time)
    #pragma unroll
    for (int j8 = 0; j8 < 8; j8++) {
        const int jk = jkQ * 128 + jhalf * 64 + j8 * 8 + 2 * t;
        float* p0 = &g_sb[0][(size_t)arow * JK_ + jk];
        float* p1 = &g_sb[0][(size_t)(arow + 8) * JK_ + jk];
        redf(p0,     s0r[j8][0] * 0.03125f);
        redf(p0 + 1, s0r[j8][1] * 0.03125f);
        redf(p1,     s0r[j8][2] * 0.03125f);
        redf(p1 + 1, s0r[j8][3] * 0.03125f);
    }
}

// ---------------- fused squash + routing pass (R12, measured 72.7us) -------
__global__ void __launch_bounds__(256, 2)
k_route(int ia, int ib, int io, int two) {
    extern __shared__ float smr[];
    float* V_sm = smr;            // 1024 floats
    float* ws   = smr + 1024;     // 8192 floats
    float* ring = smr + 9216;     // 16384 floats

    const float* sa = g_sb[ia];
    const float* sb = g_sb[ib];
    float* sout = g_sb[io];

    const int chunk = blockIdx.x;      // 0..31
    const int b     = blockIdx.y;      // 0..63
    const int tid   = threadIdx.x;     // 256
    const int warp  = tid >> 5;
    const int lane  = tid & 31;

    #pragma unroll
    for (int r = 0; r < 4; r++) {
        int j = warp * 4 + r;
        float va = sa[b * JK_ + j * 32 + lane];
        float sq = va * va;
        #pragma unroll
        for (int o = 16; o; o >>= 1) sq += __shfl_xor_sync(0xffffffffu, sq, o);
        float val = (sq / ((1.0f + sq) * sqrtf(sq + 1e-7f))) * va;
        if (two) {
            float vb = sb[b * JK_ + j * 32 + lane];
            float sqb = vb * vb;
            #pragma unroll
            for (int o = 16; o; o >>= 1) sqb += __shfl_xor_sync(0xffffffffu, sqb, o);
            val += (sqb / ((1.0f + sqb) * sqrtf(sqb + 1e-7f))) * vb;
        }
        V_sm[j * 32 + lane] = val;
    }
    __syncthreads();

    ull vq[4][4];
    #pragma unroll
    for (int q = 0; q < 4; q++) {
        float4 a = *reinterpret_cast<const float4*>(V_sm + q * 256 + lane * 8);
        float4 c = *reinterpret_cast<const float4*>(V_sm + q * 256 + lane * 8 + 4);
        vq[q][0] = packf2(a.x, a.y); vq[q][1] = packf2(a.z, a.w);
        vq[q][2] = packf2(c.x, c.y); vq[q][3] = packf2(c.z, c.w);
    }

    ull sacc[4][4];
    #pragma unroll
    for (int q = 0; q < 4; q++)
        #pragma unroll
        for (int m = 0; m < 4; m++) sacc[q][m] = 0ull;

    const char* row0 = reinterpret_cast<const char*>(
        g_uhat + ((size_t)b * N_ + (size_t)(chunk * 64 + warp * 8)) * JK_) + lane * 16;
    const uint32_t rbase = smem_u32(ring) + warp * 8192 + lane * 16;

    #pragma unroll
    for (int r = 0; r < 4; r++) {
        #pragma unroll
        for (int q = 0; q < 4; q++)
            cp_async16(rbase + r * 2048 + q * 512, row0 + (size_t)r * 2048 + q * 512);
        cp_commit();
    }

    #pragma unroll
    for (int r = 0; r < 8; r++) {
        if (r <= 4)      cp_wait<3>();
        else if (r == 5) cp_wait<2>();
        else if (r == 6) cp_wait<1>();
        else             cp_wait<0>();

        const float* slot = ring + (size_t)(warp * 2048 + (r & 3) * 512) + lane * 4;
        uint4 c4[4];
        #pragma unroll
        for (int q = 0; q < 4; q++)
            c4[q] = *reinterpret_cast<const uint4*>(slot + q * 128);

        if (r < 4) {
            #pragma unroll
            for (int q = 0; q < 4; q++)
                cp_async16(rbase + (r & 3) * 2048 + q * 512,
                           row0 + (size_t)(r + 4) * 2048 + q * 512);
            cp_commit();
        }

        float e[4];
        #pragma unroll
        for (int q = 0; q < 4; q++) {
            ull u0 = h2f2(c4[q].x), u1 = h2f2(c4[q].y);
            ull u2 = h2f2(c4[q].z), u3 = h2f2(c4[q].w);
            ull d = fma2(u0, vq[q][0], fma2(u1, vq[q][1],
                    fma2(u2, vq[q][2], fma2(u3, vq[q][3], 0ull))));
            float2 df = ull2f2(d);
            float bp = df.x + df.y;
            bp += __shfl_xor_sync(0xffffffffu, bp, 1);
            bp += __shfl_xor_sync(0xffffffffu, bp, 2);
            e[q] = __expf(bp);
        }
        float tot = e[0] + e[1] + e[2] + e[3];
        tot += __shfl_xor_sync(0xffffffffu, tot, 4);
        tot += __shfl_xor_sync(0xffffffffu, tot, 8);
        tot += __shfl_xor_sync(0xffffffffu, tot, 16);
        float inv = __fdividef(1.0f, tot);
        #pragma unroll
        for (int q = 0; q < 4; q++) {
            ull cq2 = dupf(e[q] * inv);
            ull u0 = h2f2(c4[q].x), u1 = h2f2(c4[q].y);
            ull u2 = h2f2(c4[q].z), u3 = h2f2(c4[q].w);
            sacc[q][0] = fma2(cq2, u0, sacc[q][0]);
            sacc[q][1] = fma2(cq2, u1, sacc[q][1]);
            sacc[q][2] = fma2(cq2, u2, sacc[q][2]);
            sacc[q][3] = fma2(cq2, u3, sacc[q][3]);
        }
    }

    #pragma unroll
    for (int q = 0; q < 4; q++) {
        float2 f0 = ull2f2(sacc[q][0]), f1 = ull2f2(sacc[q][1]);
        float2 f2 = ull2f2(sacc[q][2]), f3 = ull2f2(sacc[q][3]);
        float* wp = ws + warp * 1024 + q * 256 + lane * 8;
        *reinterpret_cast<float4*>(wp)     = make_float4(f0.x, f0.y, f1.x, f1.y);
        *reinterpret_cast<float4*>(wp + 4) = make_float4(f2.x, f2.y, f3.x, f3.y);
    }
    __syncthreads();

    float4 a = *reinterpret_cast<const float4*>(ws + tid * 4);
    #pragma unroll
    for (int w2 = 1; w2 < 8; w2++) {
        float4 x = *reinterpret_cast<const float4*>(ws + w2 * 1024 + tid * 4);
        a.x += x.x; a.y += x.y; a.z += x.z; a.w += x.w;
    }
    red4(sout + b * JK_ + tid * 4, a);
}

// ---------------- final squash ----------------
__global__ void __launch_bounds__(1024) k_squash_final(float* __restrict__ out) {
    const int b   = blockIdx.x;
    const int tid = threadIdx.x;
    float sv = g_sb[2][b * JK_ + tid];
    float sq = sv * sv;
    #pragma unroll
    for (int o = 16; o; o >>= 1) sq += __shfl_xor_sync(0xffffffffu, sq, o);
    out[b * JK_ + tid] = (sq / ((1.0f + sq) * sqrtf(sq + 1e-7f))) * sv;
}

extern "C" void kernel_launch(void* const* d_in, const int* in_sizes, int n_in,
                              void* d_out, int out_size) {
    const float* inp = (const float*)d_in[0];   // [64, 2048, 16]
    const float* W   = (const float*)d_in[1];   // [32, 2048, 32, 16]
    float* out = (float*)d_out;                 // [64, 32, 32]

    cudaFuncSetAttribute(k_route, cudaFuncAttributeMaxDynamicSharedMemorySize, 102400);

    k_init<<<192, 1024>>>();                            // zero s0,s1,s2
    k_uhat<<<1184, 256>>>(inp, W);                      // HMMA u_hat + s0
    k_route<<<dim3(32, 64), 256, 102400>>>(0, 0, 1, 0); // V0 -> s1
    k_route<<<dim3(32, 64), 256, 102400>>>(0, 1, 2, 1); // V0+V1 -> s2
    k_squash_final<<<64, 1024>>>(out);
}